// round 1
// baseline (speedup 1.0000x reference)
#include <cuda_runtime.h>
#include <math.h>

// Problem constants
#define B_  4
#define T_  2048
#define C_  1024
#define NH  16
#define HS  64
#define C3  3072   // 3*C

// Scratch (no allocations allowed): qkv = 96 MB, y = 32 MB
__device__ float g_qkv[B_ * T_ * C3];
__device__ float g_y[B_ * T_ * C_];

// ---------------------------------------------------------------------------
// SGEMM: C[M,N] = A[M,K] * B[N,K]^T   (both A and B are K-contiguous row-major)
// 128x128 block tile, BK=8, 256 threads, 8x8 per-thread register tile.
// ---------------------------------------------------------------------------
__global__ __launch_bounds__(256) void sgemm_nt(
    const float* __restrict__ A, const float* __restrict__ Bm,
    float* __restrict__ Cm, int M, int N, int K)
{
    __shared__ float As[8][128];
    __shared__ float Bs[8][128];

    const int t  = threadIdx.x;
    const int m0 = blockIdx.y * 128;
    const int n0 = blockIdx.x * 128;
    const int lr = t >> 1;           // 0..127 (row within tile for loading)
    const int lc = (t & 1) << 2;     // 0 or 4 (k offset for loading)
    const int tx = t & 15;           // 0..15
    const int ty = t >> 4;           // 0..15

    float acc[8][8];
#pragma unroll
    for (int i = 0; i < 8; i++)
#pragma unroll
        for (int j = 0; j < 8; j++) acc[i][j] = 0.f;

    const float* Ap = A  + (long)(m0 + lr) * K + lc;
    const float* Bp = Bm + (long)(n0 + lr) * K + lc;

    for (int k0 = 0; k0 < K; k0 += 8) {
        float4 av = *(const float4*)(Ap + k0);
        float4 bv = *(const float4*)(Bp + k0);
        As[lc + 0][lr] = av.x; As[lc + 1][lr] = av.y;
        As[lc + 2][lr] = av.z; As[lc + 3][lr] = av.w;
        Bs[lc + 0][lr] = bv.x; Bs[lc + 1][lr] = bv.y;
        Bs[lc + 2][lr] = bv.z; Bs[lc + 3][lr] = bv.w;
        __syncthreads();

#pragma unroll
        for (int kk = 0; kk < 8; kk++) {
            float4 a0 = *(const float4*)&As[kk][ty * 4];
            float4 a1 = *(const float4*)&As[kk][64 + ty * 4];
            float4 b0 = *(const float4*)&Bs[kk][tx * 4];
            float4 b1 = *(const float4*)&Bs[kk][64 + tx * 4];
            float ra[8] = {a0.x, a0.y, a0.z, a0.w, a1.x, a1.y, a1.z, a1.w};
            float rb[8] = {b0.x, b0.y, b0.z, b0.w, b1.x, b1.y, b1.z, b1.w};
#pragma unroll
            for (int i = 0; i < 8; i++)
#pragma unroll
                for (int j = 0; j < 8; j++)
                    acc[i][j] = fmaf(ra[i], rb[j], acc[i][j]);
        }
        __syncthreads();
    }

#pragma unroll
    for (int i = 0; i < 8; i++) {
        int row = m0 + ((i < 4) ? (ty * 4 + i) : (64 + ty * 4 + i - 4));
        float* cp = Cm + (long)row * N + n0;
        *(float4*)(cp + tx * 4)      = make_float4(acc[i][0], acc[i][1], acc[i][2], acc[i][3]);
        *(float4*)(cp + 64 + tx * 4) = make_float4(acc[i][4], acc[i][5], acc[i][6], acc[i][7]);
    }
}

// ---------------------------------------------------------------------------
// Fused causal flash attention (fp32). One block = 128 q rows of one (b,h).
// One thread = one q row; q and o accumulator in registers; K/V tiles of 64
// rows in SMEM (broadcast reads); online softmax with 16-column chunks.
// ---------------------------------------------------------------------------
__global__ __launch_bounds__(128) void attn_kernel(
    const float* __restrict__ qkv, float* __restrict__ y)
{
    __shared__ float Ks[64][68];   // +4 pad: avoids store bank conflicts
    __shared__ float Vs[64][68];
    __shared__ float Ss[128][17];  // per-thread scratch row for s chunk

    const int qt = (int)gridDim.x - 1 - (int)blockIdx.x;  // heavy tiles first
    const int h  = blockIdx.y;
    const int b  = blockIdx.z;
    const int t  = threadIdx.x;
    const int qr = qt * 128 + t;               // global q row for this thread

    const float* base = qkv + (long)b * T_ * C3;

    // q row -> registers (16 x float4)
    const float4* qp = (const float4*)(base + (long)qr * C3 + h * HS);
    float4 q4[16];
#pragma unroll
    for (int i = 0; i < 16; i++) q4[i] = qp[i];

    float4 o4[16];
#pragma unroll
    for (int i = 0; i < 16; i++) o4[i] = make_float4(0.f, 0.f, 0.f, 0.f);

    float m = -INFINITY, l = 0.f;

    const int row = t >> 1;          // K/V load row (0..63)
    const int d0  = (t & 1) * 32;    // K/V load half
    const int ntiles = 2 * qt + 2;   // causal: tiles 0..2qt+1

    for (int kt = 0; kt < ntiles; kt++) {
        const float4* kp = (const float4*)(base + (long)(kt * 64 + row) * C3 + C_     + h * HS + d0);
        const float4* vp = (const float4*)(base + (long)(kt * 64 + row) * C3 + 2 * C_ + h * HS + d0);
#pragma unroll
        for (int i = 0; i < 8; i++) {
            *(float4*)&Ks[row][d0 + 4 * i] = kp[i];
            *(float4*)&Vs[row][d0 + 4 * i] = vp[i];
        }
        __syncthreads();

#pragma unroll 1
        for (int ch = 0; ch < 4; ch++) {
            const int cbase = kt * 64 + ch * 16;

            // ---- S = q . K^T for 16 columns, causal mask, track chunk max
            float cmax = -INFINITY;
#pragma unroll 1
            for (int i = 0; i < 16; i++) {
                const float4* kr = (const float4*)&Ks[ch * 16 + i][0];
                float a0 = 0.f, a1 = 0.f, a2 = 0.f, a3 = 0.f;
#pragma unroll
                for (int dd = 0; dd < 16; dd += 4) {
                    float4 k0v = kr[dd + 0], k1v = kr[dd + 1];
                    float4 k2v = kr[dd + 2], k3v = kr[dd + 3];
                    a0 = fmaf(q4[dd + 0].x, k0v.x, a0); a0 = fmaf(q4[dd + 0].y, k0v.y, a0);
                    a0 = fmaf(q4[dd + 0].z, k0v.z, a0); a0 = fmaf(q4[dd + 0].w, k0v.w, a0);
                    a1 = fmaf(q4[dd + 1].x, k1v.x, a1); a1 = fmaf(q4[dd + 1].y, k1v.y, a1);
                    a1 = fmaf(q4[dd + 1].z, k1v.z, a1); a1 = fmaf(q4[dd + 1].w, k1v.w, a1);
                    a2 = fmaf(q4[dd + 2].x, k2v.x, a2); a2 = fmaf(q4[dd + 2].y, k2v.y, a2);
                    a2 = fmaf(q4[dd + 2].z, k2v.z, a2); a2 = fmaf(q4[dd + 2].w, k2v.w, a2);
                    a3 = fmaf(q4[dd + 3].x, k3v.x, a3); a3 = fmaf(q4[dd + 3].y, k3v.y, a3);
                    a3 = fmaf(q4[dd + 3].z, k3v.z, a3); a3 = fmaf(q4[dd + 3].w, k3v.w, a3);
                }
                float sv = (a0 + a1) + (a2 + a3);
                sv = (cbase + i <= qr) ? sv * 0.125f : -INFINITY;  // 1/sqrt(64)
                Ss[t][i] = sv;
                cmax = fmaxf(cmax, sv);
            }

            // ---- online softmax update
            const float mnew  = fmaxf(m, cmax);
            const float scale = __expf(m - mnew);  // exp(-inf)=0 on first chunk: o is 0 anyway
            m = mnew;
            l *= scale;
#pragma unroll
            for (int i = 0; i < 16; i++) {
                o4[i].x *= scale; o4[i].y *= scale;
                o4[i].z *= scale; o4[i].w *= scale;
            }
            float psum = 0.f;
#pragma unroll 1
            for (int i = 0; i < 16; i++) {
                float p = __expf(Ss[t][i] - m);    // masked -> exp(-inf)=0
                Ss[t][i] = p;
                psum += p;
            }
            l += psum;

            // ---- O += P * V
#pragma unroll 1
            for (int i = 0; i < 16; i++) {
                const float p = Ss[t][i];
                const float4* vr = (const float4*)&Vs[ch * 16 + i][0];
#pragma unroll
                for (int dd = 0; dd < 16; dd++) {
                    float4 vv = vr[dd];
                    o4[dd].x = fmaf(p, vv.x, o4[dd].x);
                    o4[dd].y = fmaf(p, vv.y, o4[dd].y);
                    o4[dd].z = fmaf(p, vv.z, o4[dd].z);
                    o4[dd].w = fmaf(p, vv.w, o4[dd].w);
                }
            }
        }
        __syncthreads();
    }

    const float inv = 1.f / l;
    float4* yp = (float4*)(y + (long)(b * T_ + qr) * C_ + h * HS);
#pragma unroll
    for (int i = 0; i < 16; i++)
        yp[i] = make_float4(o4[i].x * inv, o4[i].y * inv, o4[i].z * inv, o4[i].w * inv);
}

// ---------------------------------------------------------------------------
// Launch: qkv GEMM -> fused attention -> projection GEMM
// ---------------------------------------------------------------------------
extern "C" void kernel_launch(void* const* d_in, const int* in_sizes, int n_in,
                              void* d_out, int out_size)
{
    const float* x    = (const float*)d_in[0];   // [4,2048,1024]
    const float* watt = (const float*)d_in[1];   // [3072,1024]
    const float* wprj = (const float*)d_in[2];   // [1024,1024]
    float* out = (float*)d_out;                  // [4,2048,1024]

    float *qkv, *y;
    cudaGetSymbolAddress((void**)&qkv, g_qkv);
    cudaGetSymbolAddress((void**)&y,   g_y);

    // Stage 1: qkv = x @ w_attn^T   (M=8192, N=3072, K=1024)
    dim3 g1(C3 / 128, (B_ * T_) / 128);
    sgemm_nt<<<g1, 256>>>(x, watt, qkv, B_ * T_, C3, C_);

    // Stage 2: fused causal attention -> y [B,T,C]
    dim3 g2(T_ / 128, NH, B_);
    attn_kernel<<<g2, 128>>>(qkv, y);

    // Stage 3: out = y @ w_proj^T   (M=8192, N=1024, K=1024)
    dim3 g3(C_ / 128, (B_ * T_) / 128);
    sgemm_nt<<<g3, 256>>>(y, wprj, out, B_ * T_, C_, C_);
}

// round 6
// speedup vs baseline: 1.2491x; 1.2491x over previous
#include <cuda_runtime.h>
#include <math.h>

// Problem constants
#define B_  4
#define T_  2048
#define C_  1024
#define NH  16
#define HS  64
#define C3  3072   // 3*C

// Scratch (no allocations allowed)
__device__ float g_qkv[B_ * T_ * C3];
__device__ float g_y[B_ * T_ * C_];

// ---------------------------------------------------------------------------
// bf16x3 split GEMM: C[M,N] = A[M,K] * B[N,K]^T (both K-contiguous), fp32 in,
// fp32 out, near-fp32 accuracy via error-compensated bf16 split:
//   a = ah + al   (ah = fp32 truncated to top 16 bits = exact bf16;
//                  al = a - ah exact in fp32, then rounded to bf16)
//   C ~= Ah Bh + Al Bh + Ah Bl     (Al*Bl dropped: ~2^-16 relative)
// 128x128 block tile, BK=16, 256 threads, 8 warps (2x4), 64x32 warp tile.
// SMEM row = 16 words; k-pair jp (=k/2, 0..7) stored as bf16x2:
//   hi word at ((jp&3)^swz)*4 + (jp>>2), lo word at +2
// so one LDS.128 per row gives {hi_g, hi_{g+4}, lo_g, lo_{g+4}} = exactly the
// m16n8k16 fragment registers for the hi and lo terms.
// ---------------------------------------------------------------------------
__device__ __forceinline__ void bf16x3_store_pair(
    float* __restrict__ S, int row, int swz, int jp, float x0, float x1)
{
    const unsigned w0 = __float_as_uint(x0);
    const unsigned w1 = __float_as_uint(x1);
    const unsigned hw = (w0 >> 16) | (w1 & 0xffff0000u);   // {lo16=bf16(x0), hi16=bf16(x1)}
    const float h0 = __uint_as_float(w0 & 0xffff0000u);
    const float h1 = __uint_as_float(w1 & 0xffff0000u);
    const float r0 = x0 - h0;   // exact
    const float r1 = x1 - h1;   // exact
    unsigned lw;
    asm("cvt.rn.bf16x2.f32 %0, %1, %2;" : "=r"(lw) : "f"(r1), "f"(r0));
    const int base = row * 16 + (((jp & 3) ^ swz) << 2) + (jp >> 2);
    S[base]     = __uint_as_float(hw);
    S[base + 2] = __uint_as_float(lw);
}

__device__ __forceinline__ void mma_bf16(
    float* d, unsigned a0, unsigned a1, unsigned a2, unsigned a3,
    unsigned b0, unsigned b1)
{
    asm volatile(
        "mma.sync.aligned.m16n8k16.row.col.f32.bf16.bf16.f32 "
        "{%0,%1,%2,%3}, {%4,%5,%6,%7}, {%8,%9}, {%0,%1,%2,%3};\n"
        : "+f"(d[0]), "+f"(d[1]), "+f"(d[2]), "+f"(d[3])
        : "r"(a0), "r"(a1), "r"(a2), "r"(a3), "r"(b0), "r"(b1));
}

__global__ __launch_bounds__(256) void bf16x3_gemm_nt(
    const float* __restrict__ A, const float* __restrict__ Bm,
    float* __restrict__ Cm, int M, int N, int K)
{
    __shared__ float As[128 * 16];
    __shared__ float Bs[128 * 16];

    const int tid  = threadIdx.x;
    const int lane = tid & 31;
    const int warp = tid >> 5;
    const int wm   = (warp >> 2) * 64;   // warp m offset
    const int wn   = (warp & 3) * 32;    // warp n offset
    const int gid  = lane >> 2;          // 0..7
    const int ctid = lane & 3;           // 0..3

    const int m0 = blockIdx.y * 128;
    const int n0 = blockIdx.x * 128;

    const int lrow = tid >> 1;                 // 0..127
    const int lq0  = (tid & 1) * 2;            // quarter 0 or 2 (k = q*4..q*4+7)
    const int swzs = (lrow ^ (lrow >> 2)) & 3;

    const float* Ag = A  + (long)(m0 + lrow) * K + lq0 * 4;
    const float* Bg = Bm + (long)(n0 + lrow) * K + lq0 * 4;

    float acc[4][4][4];
#pragma unroll
    for (int i = 0; i < 4; i++)
#pragma unroll
        for (int j = 0; j < 4; j++)
#pragma unroll
            for (int r = 0; r < 4; r++) acc[i][j][r] = 0.f;

    const int nstages = K / 16;

    float4 pa0 = *(const float4*)(Ag);
    float4 pa1 = *(const float4*)(Ag + 4);
    float4 pb0 = *(const float4*)(Bg);
    float4 pb1 = *(const float4*)(Bg + 4);

    for (int s = 0; s < nstages; s++) {
        __syncthreads();
        // convert + store prefetched tile (pairs jp = 2q + {0,1})
        {
            bf16x3_store_pair(As, lrow, swzs, 2 * lq0 + 0, pa0.x, pa0.y);
            bf16x3_store_pair(As, lrow, swzs, 2 * lq0 + 1, pa0.z, pa0.w);
            bf16x3_store_pair(As, lrow, swzs, 2 * lq0 + 2, pa1.x, pa1.y);
            bf16x3_store_pair(As, lrow, swzs, 2 * lq0 + 3, pa1.z, pa1.w);
            bf16x3_store_pair(Bs, lrow, swzs, 2 * lq0 + 0, pb0.x, pb0.y);
            bf16x3_store_pair(Bs, lrow, swzs, 2 * lq0 + 1, pb0.z, pb0.w);
            bf16x3_store_pair(Bs, lrow, swzs, 2 * lq0 + 2, pb1.x, pb1.y);
            bf16x3_store_pair(Bs, lrow, swzs, 2 * lq0 + 3, pb1.z, pb1.w);
        }
        __syncthreads();

        // prefetch next tile (clamped; values unused on last iter)
        {
            const long off = (s + 1 < nstages) ? (long)(s + 1) * 16 : 0;
            pa0 = *(const float4*)(Ag + off);
            pa1 = *(const float4*)(Ag + off + 4);
            pb0 = *(const float4*)(Bg + off);
            pb1 = *(const float4*)(Bg + off + 4);
        }

        // fragment loads: one LDS.128 per row
        float4 af[4][2];
        float4 bf[4];
#pragma unroll
        for (int mt = 0; mt < 4; mt++) {
            const int r0 = wm + mt * 16 + gid;
            const int r1 = r0 + 8;
            const int g0 = ctid ^ ((r0 ^ (r0 >> 2)) & 3);
            const int g1 = ctid ^ ((r1 ^ (r1 >> 2)) & 3);
            af[mt][0] = *(const float4*)&As[r0 * 16 + (g0 << 2)];
            af[mt][1] = *(const float4*)&As[r1 * 16 + (g1 << 2)];
        }
#pragma unroll
        for (int nt = 0; nt < 4; nt++) {
            const int rb = wn + nt * 8 + gid;
            const int gb = ctid ^ ((rb ^ (rb >> 2)) & 3);
            bf[nt] = *(const float4*)&Bs[rb * 16 + (gb << 2)];
        }

        // 48 mma per warp: 3 terms x 4mt x 4nt of m16n8k16
#pragma unroll
        for (int mt = 0; mt < 4; mt++) {
            const unsigned ah0 = __float_as_uint(af[mt][0].x);
            const unsigned ah1 = __float_as_uint(af[mt][1].x);
            const unsigned ah2 = __float_as_uint(af[mt][0].y);
            const unsigned ah3 = __float_as_uint(af[mt][1].y);
            const unsigned al0 = __float_as_uint(af[mt][0].z);
            const unsigned al1 = __float_as_uint(af[mt][1].z);
            const unsigned al2 = __float_as_uint(af[mt][0].w);
            const unsigned al3 = __float_as_uint(af[mt][1].w);
#pragma unroll
            for (int nt = 0; nt < 4; nt++) {
                float* d = acc[mt][nt];
                const unsigned bh0 = __float_as_uint(bf[nt].x);
                const unsigned bh1 = __float_as_uint(bf[nt].y);
                const unsigned bl0 = __float_as_uint(bf[nt].z);
                const unsigned bl1 = __float_as_uint(bf[nt].w);
                mma_bf16(d, ah0, ah1, ah2, ah3, bh0, bh1);   // Ah*Bh
                mma_bf16(d, al0, al1, al2, al3, bh0, bh1);   // Al*Bh
                mma_bf16(d, ah0, ah1, ah2, ah3, bl0, bl1);   // Ah*Bl
            }
        }
    }

    // epilogue (m16n8 D layout): c0,c1 -> row gid cols 2ctid..+1; c2,c3 -> row gid+8
#pragma unroll
    for (int mt = 0; mt < 4; mt++) {
        const int r0 = m0 + wm + mt * 16 + gid;
#pragma unroll
        for (int nt = 0; nt < 4; nt++) {
            const int c = n0 + wn + nt * 8 + 2 * ctid;
            *(float2*)(Cm + (long)r0 * N + c)       = make_float2(acc[mt][nt][0], acc[mt][nt][1]);
            *(float2*)(Cm + (long)(r0 + 8) * N + c) = make_float2(acc[mt][nt][2], acc[mt][nt][3]);
        }
    }
}

// ---------------------------------------------------------------------------
// Fused causal flash attention (fp32) — unchanged from R1 (validated).
// ---------------------------------------------------------------------------
__global__ __launch_bounds__(128) void attn_kernel(
    const float* __restrict__ qkv, float* __restrict__ y)
{
    __shared__ float Ks[64][68];
    __shared__ float Vs[64][68];
    __shared__ float Ss[128][17];

    const int qt = (int)gridDim.x - 1 - (int)blockIdx.x;
    const int h  = blockIdx.y;
    const int b  = blockIdx.z;
    const int t  = threadIdx.x;
    const int qr = qt * 128 + t;

    const float* base = qkv + (long)b * T_ * C3;

    const float4* qp = (const float4*)(base + (long)qr * C3 + h * HS);
    float4 q4[16];
#pragma unroll
    for (int i = 0; i < 16; i++) q4[i] = qp[i];

    float4 o4[16];
#pragma unroll
    for (int i = 0; i < 16; i++) o4[i] = make_float4(0.f, 0.f, 0.f, 0.f);

    float m = -INFINITY, l = 0.f;

    const int row = t >> 1;
    const int d0  = (t & 1) * 32;
    const int ntiles = 2 * qt + 2;

    for (int kt = 0; kt < ntiles; kt++) {
        const float4* kp = (const float4*)(base + (long)(kt * 64 + row) * C3 + C_     + h * HS + d0);
        const float4* vp = (const float4*)(base + (long)(kt * 64 + row) * C3 + 2 * C_ + h * HS + d0);
#pragma unroll
        for (int i = 0; i < 8; i++) {
            *(float4*)&Ks[row][d0 + 4 * i] = kp[i];
            *(float4*)&Vs[row][d0 + 4 * i] = vp[i];
        }
        __syncthreads();

#pragma unroll 1
        for (int ch = 0; ch < 4; ch++) {
            const int cbase = kt * 64 + ch * 16;

            float cmax = -INFINITY;
#pragma unroll 1
            for (int i = 0; i < 16; i++) {
                const float4* kr = (const float4*)&Ks[ch * 16 + i][0];
                float a0 = 0.f, a1 = 0.f, a2 = 0.f, a3 = 0.f;
#pragma unroll
                for (int dd = 0; dd < 16; dd += 4) {
                    float4 k0v = kr[dd + 0], k1v = kr[dd + 1];
                    float4 k2v = kr[dd + 2], k3v = kr[dd + 3];
                    a0 = fmaf(q4[dd + 0].x, k0v.x, a0); a0 = fmaf(q4[dd + 0].y, k0v.y, a0);
                    a0 = fmaf(q4[dd + 0].z, k0v.z, a0); a0 = fmaf(q4[dd + 0].w, k0v.w, a0);
                    a1 = fmaf(q4[dd + 1].x, k1v.x, a1); a1 = fmaf(q4[dd + 1].y, k1v.y, a1);
                    a1 = fmaf(q4[dd + 1].z, k1v.z, a1); a1 = fmaf(q4[dd + 1].w, k1v.w, a1);
                    a2 = fmaf(q4[dd + 2].x, k2v.x, a2); a2 = fmaf(q4[dd + 2].y, k2v.y, a2);
                    a2 = fmaf(q4[dd + 2].z, k2v.z, a2); a2 = fmaf(q4[dd + 2].w, k2v.w, a2);
                    a3 = fmaf(q4[dd + 3].x, k3v.x, a3); a3 = fmaf(q4[dd + 3].y, k3v.y, a3);
                    a3 = fmaf(q4[dd + 3].z, k3v.z, a3); a3 = fmaf(q4[dd + 3].w, k3v.w, a3);
                }
                float sv = (a0 + a1) + (a2 + a3);
                sv = (cbase + i <= qr) ? sv * 0.125f : -INFINITY;
                Ss[t][i] = sv;
                cmax = fmaxf(cmax, sv);
            }

            const float mnew  = fmaxf(m, cmax);
            const float scale = __expf(m - mnew);
            m = mnew;
            l *= scale;
#pragma unroll
            for (int i = 0; i < 16; i++) {
                o4[i].x *= scale; o4[i].y *= scale;
                o4[i].z *= scale; o4[i].w *= scale;
            }
            float psum = 0.f;
#pragma unroll 1
            for (int i = 0; i < 16; i++) {
                float p = __expf(Ss[t][i] - m);
                Ss[t][i] = p;
                psum += p;
            }
            l += psum;

#pragma unroll 1
            for (int i = 0; i < 16; i++) {
                const float p = Ss[t][i];
                const float4* vr = (const float4*)&Vs[ch * 16 + i][0];
#pragma unroll
                for (int dd = 0; dd < 16; dd++) {
                    float4 vv = vr[dd];
                    o4[dd].x = fmaf(p, vv.x, o4[dd].x);
                    o4[dd].y = fmaf(p, vv.y, o4[dd].y);
                    o4[dd].z = fmaf(p, vv.z, o4[dd].z);
                    o4[dd].w = fmaf(p, vv.w, o4[dd].w);
                }
            }
        }
        __syncthreads();
    }

    const float inv = 1.f / l;
    float4* yp = (float4*)(y + (long)(b * T_ + qr) * C_ + h * HS);
#pragma unroll
    for (int i = 0; i < 16; i++)
        yp[i] = make_float4(o4[i].x * inv, o4[i].y * inv, o4[i].z * inv, o4[i].w * inv);
}

// ---------------------------------------------------------------------------
extern "C" void kernel_launch(void* const* d_in, const int* in_sizes, int n_in,
                              void* d_out, int out_size)
{
    const float* x    = (const float*)d_in[0];
    const float* watt = (const float*)d_in[1];
    const float* wprj = (const float*)d_in[2];
    float* out = (float*)d_out;

    float *qkv, *y;
    cudaGetSymbolAddress((void**)&qkv, g_qkv);
    cudaGetSymbolAddress((void**)&y,   g_y);

    dim3 g1(C3 / 128, (B_ * T_) / 128);
    bf16x3_gemm_nt<<<g1, 256>>>(x, watt, qkv, B_ * T_, C3, C_);

    dim3 g2(T_ / 128, NH, B_);
    attn_kernel<<<g2, 128>>>(qkv, y);

    dim3 g3(C_ / 128, (B_ * T_) / 128);
    bf16x3_gemm_nt<<<g3, 256>>>(y, wprj, out, B_ * T_, C_, C_);
}

// round 7
// speedup vs baseline: 2.3101x; 1.8494x over previous
#include <cuda_runtime.h>
#include <math.h>

// Problem constants
#define B_  4
#define T_  2048
#define C_  1024
#define NH  16
#define HS  64
#define C3  3072   // 3*C

// Scratch (no allocations allowed)
__device__ float g_qkv[B_ * T_ * C3];
__device__ float g_y[B_ * T_ * C_];

// ---------------------------------------------------------------------------
// bf16x3 helpers (validated in R6)
// ---------------------------------------------------------------------------
__device__ __forceinline__ void bf16x3_store_pair(
    float* __restrict__ S, int row, int swz, int jp, float x0, float x1)
{
    const unsigned w0 = __float_as_uint(x0);
    const unsigned w1 = __float_as_uint(x1);
    const unsigned hw = (w0 >> 16) | (w1 & 0xffff0000u);
    const float r0 = x0 - __uint_as_float(w0 & 0xffff0000u);   // exact
    const float r1 = x1 - __uint_as_float(w1 & 0xffff0000u);   // exact
    unsigned lw;
    asm("cvt.rn.bf16x2.f32 %0, %1, %2;" : "=r"(lw) : "f"(r1), "f"(r0));
    const int base = row * 16 + (((jp & 3) ^ swz) << 2) + (jp >> 2);
    S[base]     = __uint_as_float(hw);
    S[base + 2] = __uint_as_float(lw);
}

__device__ __forceinline__ void split2(float x0, float x1, unsigned& hw, unsigned& lw)
{
    const unsigned w0 = __float_as_uint(x0);
    const unsigned w1 = __float_as_uint(x1);
    hw = (w0 >> 16) | (w1 & 0xffff0000u);
    const float r0 = x0 - __uint_as_float(w0 & 0xffff0000u);
    const float r1 = x1 - __uint_as_float(w1 & 0xffff0000u);
    asm("cvt.rn.bf16x2.f32 %0, %1, %2;" : "=r"(lw) : "f"(r1), "f"(r0));
}

__device__ __forceinline__ void mma_bf16(
    float* d, unsigned a0, unsigned a1, unsigned a2, unsigned a3,
    unsigned b0, unsigned b1)
{
    asm volatile(
        "mma.sync.aligned.m16n8k16.row.col.f32.bf16.bf16.f32 "
        "{%0,%1,%2,%3}, {%4,%5,%6,%7}, {%8,%9}, {%0,%1,%2,%3};\n"
        : "+f"(d[0]), "+f"(d[1]), "+f"(d[2]), "+f"(d[3])
        : "r"(a0), "r"(a1), "r"(a2), "r"(a3), "r"(b0), "r"(b1));
}

// ---------------------------------------------------------------------------
// bf16x3 split GEMM (unchanged from R6, validated: rel_err 4.7e-5)
// ---------------------------------------------------------------------------
__global__ __launch_bounds__(256) void bf16x3_gemm_nt(
    const float* __restrict__ A, const float* __restrict__ Bm,
    float* __restrict__ Cm, int M, int N, int K)
{
    __shared__ float As[128 * 16];
    __shared__ float Bs[128 * 16];

    const int tid  = threadIdx.x;
    const int lane = tid & 31;
    const int warp = tid >> 5;
    const int wm   = (warp >> 2) * 64;
    const int wn   = (warp & 3) * 32;
    const int gid  = lane >> 2;
    const int ctid = lane & 3;

    const int m0 = blockIdx.y * 128;
    const int n0 = blockIdx.x * 128;

    const int lrow = tid >> 1;
    const int lq0  = (tid & 1) * 2;
    const int swzs = (lrow ^ (lrow >> 2)) & 3;

    const float* Ag = A  + (long)(m0 + lrow) * K + lq0 * 4;
    const float* Bg = Bm + (long)(n0 + lrow) * K + lq0 * 4;

    float acc[4][4][4];
#pragma unroll
    for (int i = 0; i < 4; i++)
#pragma unroll
        for (int j = 0; j < 4; j++)
#pragma unroll
            for (int r = 0; r < 4; r++) acc[i][j][r] = 0.f;

    const int nstages = K / 16;

    float4 pa0 = *(const float4*)(Ag);
    float4 pa1 = *(const float4*)(Ag + 4);
    float4 pb0 = *(const float4*)(Bg);
    float4 pb1 = *(const float4*)(Bg + 4);

    for (int s = 0; s < nstages; s++) {
        __syncthreads();
        bf16x3_store_pair(As, lrow, swzs, 2 * lq0 + 0, pa0.x, pa0.y);
        bf16x3_store_pair(As, lrow, swzs, 2 * lq0 + 1, pa0.z, pa0.w);
        bf16x3_store_pair(As, lrow, swzs, 2 * lq0 + 2, pa1.x, pa1.y);
        bf16x3_store_pair(As, lrow, swzs, 2 * lq0 + 3, pa1.z, pa1.w);
        bf16x3_store_pair(Bs, lrow, swzs, 2 * lq0 + 0, pb0.x, pb0.y);
        bf16x3_store_pair(Bs, lrow, swzs, 2 * lq0 + 1, pb0.z, pb0.w);
        bf16x3_store_pair(Bs, lrow, swzs, 2 * lq0 + 2, pb1.x, pb1.y);
        bf16x3_store_pair(Bs, lrow, swzs, 2 * lq0 + 3, pb1.z, pb1.w);
        __syncthreads();

        {
            const long off = (s + 1 < nstages) ? (long)(s + 1) * 16 : 0;
            pa0 = *(const float4*)(Ag + off);
            pa1 = *(const float4*)(Ag + off + 4);
            pb0 = *(const float4*)(Bg + off);
            pb1 = *(const float4*)(Bg + off + 4);
        }

        float4 af[4][2];
        float4 bf[4];
#pragma unroll
        for (int mt = 0; mt < 4; mt++) {
            const int r0 = wm + mt * 16 + gid;
            const int r1 = r0 + 8;
            const int g0 = ctid ^ ((r0 ^ (r0 >> 2)) & 3);
            const int g1 = ctid ^ ((r1 ^ (r1 >> 2)) & 3);
            af[mt][0] = *(const float4*)&As[r0 * 16 + (g0 << 2)];
            af[mt][1] = *(const float4*)&As[r1 * 16 + (g1 << 2)];
        }
#pragma unroll
        for (int nt = 0; nt < 4; nt++) {
            const int rb = wn + nt * 8 + gid;
            const int gb = ctid ^ ((rb ^ (rb >> 2)) & 3);
            bf[nt] = *(const float4*)&Bs[rb * 16 + (gb << 2)];
        }

#pragma unroll
        for (int mt = 0; mt < 4; mt++) {
            const unsigned ah0 = __float_as_uint(af[mt][0].x);
            const unsigned ah1 = __float_as_uint(af[mt][1].x);
            const unsigned ah2 = __float_as_uint(af[mt][0].y);
            const unsigned ah3 = __float_as_uint(af[mt][1].y);
            const unsigned al0 = __float_as_uint(af[mt][0].z);
            const unsigned al1 = __float_as_uint(af[mt][1].z);
            const unsigned al2 = __float_as_uint(af[mt][0].w);
            const unsigned al3 = __float_as_uint(af[mt][1].w);
#pragma unroll
            for (int nt = 0; nt < 4; nt++) {
                float* d = acc[mt][nt];
                const unsigned bh0 = __float_as_uint(bf[nt].x);
                const unsigned bh1 = __float_as_uint(bf[nt].y);
                const unsigned bl0 = __float_as_uint(bf[nt].z);
                const unsigned bl1 = __float_as_uint(bf[nt].w);
                mma_bf16(d, ah0, ah1, ah2, ah3, bh0, bh1);
                mma_bf16(d, al0, al1, al2, al3, bh0, bh1);
                mma_bf16(d, ah0, ah1, ah2, ah3, bl0, bl1);
            }
        }
    }

#pragma unroll
    for (int mt = 0; mt < 4; mt++) {
        const int r0 = m0 + wm + mt * 16 + gid;
#pragma unroll
        for (int nt = 0; nt < 4; nt++) {
            const int c = n0 + wn + nt * 8 + 2 * ctid;
            *(float2*)(Cm + (long)r0 * N + c)       = make_float2(acc[mt][nt][0], acc[mt][nt][1]);
            *(float2*)(Cm + (long)(r0 + 8) * N + c) = make_float2(acc[mt][nt][2], acc[mt][nt][3]);
        }
    }
}

// ---------------------------------------------------------------------------
// bf16x3 tensor-core flash attention (causal).
// Block = 128 q rows x (b,h); 8 warps, warp owns m16. Q hi/lo frags in regs.
// K tile: Ks[chunk][key][16w] (same layout as GEMM B). V tile transposed:
// Vs[keychunk][hs][16w] (pairs over keys). P frags packed from S accumulators
// in registers. Online softmax with quad shfl row-max.
// ---------------------------------------------------------------------------
__global__ __launch_bounds__(256) void attn_mma(
    const float* __restrict__ qkv, float* __restrict__ y)
{
    __shared__ float Ks[4][64][16];
    __shared__ float Vs[4][64][16];

    const int qt   = (int)gridDim.x - 1 - (int)blockIdx.x;
    const int h    = blockIdx.y;
    const int b    = blockIdx.z;
    const int tid  = threadIdx.x;
    const int lane = tid & 31;
    const int warp = tid >> 5;
    const int gid  = lane >> 2;
    const int ctid = lane & 3;
    const int qbase = qt * 128 + warp * 16;
    const int qr0 = qbase + gid;       // row for c0,c1
    const int qr1 = qr0 + 8;           // row for c2,c3

    const float* base = qkv + (long)b * T_ * C3;

    // ---- Q fragments (hi/lo), loaded once: qh[c][0..3] per hs-chunk c
    unsigned qh[4][4], ql[4][4];
#pragma unroll
    for (int c = 0; c < 4; c++) {
        const float* q0p = base + (long)qr0 * C3 + h * HS + c * 16;
        const float* q1p = base + (long)qr1 * C3 + h * HS + c * 16;
        float2 x00 = *(const float2*)(q0p + 2 * ctid);
        float2 x10 = *(const float2*)(q1p + 2 * ctid);
        float2 x01 = *(const float2*)(q0p + 8 + 2 * ctid);
        float2 x11 = *(const float2*)(q1p + 8 + 2 * ctid);
        split2(x00.x, x00.y, qh[c][0], ql[c][0]);
        split2(x10.x, x10.y, qh[c][1], ql[c][1]);
        split2(x01.x, x01.y, qh[c][2], ql[c][2]);
        split2(x11.x, x11.y, qh[c][3], ql[c][3]);
    }

    float Oa[8][4];
#pragma unroll
    for (int nt = 0; nt < 8; nt++)
#pragma unroll
        for (int r = 0; r < 4; r++) Oa[nt][r] = 0.f;
    float m0 = -INFINITY, m1 = -INFINITY, l0 = 0.f, l1 = 0.f;

    // K-tile load mapping: krow = tid>>2, chunk = tid&3
    const int krow = tid >> 2;
    const int kch  = tid & 3;
    const int kswz = (krow ^ (krow >> 2)) & 3;
    // V-tile load mapping: key pair kp = tid>>3, hs pairs {hpz, +8, +16, +24}
    const int vkp  = tid >> 3;           // 0..31
    const int hpz  = tid & 7;
    const int vck  = vkp >> 3;           // key chunk
    const int vjp  = vkp & 7;            // pair within chunk

    const int ntiles = 2 * qt + 2;

    for (int kt = 0; kt < ntiles; kt++) {
        // ---- load K tile (64 keys x 64 hs)
        {
            const float* kg = base + (long)(kt * 64 + krow) * C3 + C_ + h * HS + kch * 16;
            float4 f0 = *(const float4*)(kg);
            float4 f1 = *(const float4*)(kg + 4);
            float4 f2 = *(const float4*)(kg + 8);
            float4 f3 = *(const float4*)(kg + 12);
            float* Sc = &Ks[kch][0][0];
            bf16x3_store_pair(Sc, krow, kswz, 0, f0.x, f0.y);
            bf16x3_store_pair(Sc, krow, kswz, 1, f0.z, f0.w);
            bf16x3_store_pair(Sc, krow, kswz, 2, f1.x, f1.y);
            bf16x3_store_pair(Sc, krow, kswz, 3, f1.z, f1.w);
            bf16x3_store_pair(Sc, krow, kswz, 4, f2.x, f2.y);
            bf16x3_store_pair(Sc, krow, kswz, 5, f2.z, f2.w);
            bf16x3_store_pair(Sc, krow, kswz, 6, f3.x, f3.y);
            bf16x3_store_pair(Sc, krow, kswz, 7, f3.z, f3.w);
        }
        // ---- load V tile transposed (rows = hs, pairs over keys)
        {
            const float* v0g = base + (long)(kt * 64 + 2 * vkp) * C3 + 2 * C_ + h * HS;
            const float* v1g = v0g + C3;
            float* Sv = &Vs[vck][0][0];
#pragma unroll
            for (int i = 0; i < 4; i++) {
                const int hh = 2 * (hpz + 8 * i);
                float2 v0 = *(const float2*)(v0g + hh);
                float2 v1 = *(const float2*)(v1g + hh);
                const int sw0 = (hh ^ (hh >> 2)) & 3;
                const int sw1 = ((hh + 1) ^ ((hh + 1) >> 2)) & 3;
                bf16x3_store_pair(Sv, hh,     sw0, vjp, v0.x, v1.x);
                bf16x3_store_pair(Sv, hh + 1, sw1, vjp, v0.y, v1.y);
            }
        }
        __syncthreads();

        // warp-uniform skip: whole warp masked out for this key tile
        if (qbase + 15 >= kt * 64) {
            // ---- S = Q K^T (bf16x3)
            float Sa[8][4];
#pragma unroll
            for (int nt = 0; nt < 8; nt++)
#pragma unroll
                for (int r = 0; r < 4; r++) Sa[nt][r] = 0.f;
#pragma unroll
            for (int nt = 0; nt < 8; nt++) {
                const int rb = nt * 8 + gid;
                const int gb = ctid ^ ((rb ^ (rb >> 2)) & 3);
#pragma unroll
                for (int c = 0; c < 4; c++) {
                    float4 bv = *(const float4*)&Ks[c][rb][gb << 2];
                    const unsigned bh0 = __float_as_uint(bv.x);
                    const unsigned bh1 = __float_as_uint(bv.y);
                    const unsigned bl0 = __float_as_uint(bv.z);
                    const unsigned bl1 = __float_as_uint(bv.w);
                    mma_bf16(Sa[nt], qh[c][0], qh[c][1], qh[c][2], qh[c][3], bh0, bh1);
                    mma_bf16(Sa[nt], ql[c][0], ql[c][1], ql[c][2], ql[c][3], bh0, bh1);
                    mma_bf16(Sa[nt], qh[c][0], qh[c][1], qh[c][2], qh[c][3], bl0, bl1);
                }
            }

            // ---- scale + causal mask
            const bool need_mask = (kt >= 2 * qt);
#pragma unroll
            for (int nt = 0; nt < 8; nt++) {
                const int col = kt * 64 + nt * 8 + 2 * ctid;
                Sa[nt][0] *= 0.125f; Sa[nt][1] *= 0.125f;
                Sa[nt][2] *= 0.125f; Sa[nt][3] *= 0.125f;
                if (need_mask) {
                    if (col     > qr0) Sa[nt][0] = -INFINITY;
                    if (col + 1 > qr0) Sa[nt][1] = -INFINITY;
                    if (col     > qr1) Sa[nt][2] = -INFINITY;
                    if (col + 1 > qr1) Sa[nt][3] = -INFINITY;
                }
            }

            // ---- row max (in-thread, then across quad)
            float cm0 = -INFINITY, cm1 = -INFINITY;
#pragma unroll
            for (int nt = 0; nt < 8; nt++) {
                cm0 = fmaxf(cm0, fmaxf(Sa[nt][0], Sa[nt][1]));
                cm1 = fmaxf(cm1, fmaxf(Sa[nt][2], Sa[nt][3]));
            }
            cm0 = fmaxf(cm0, __shfl_xor_sync(0xffffffffu, cm0, 1));
            cm0 = fmaxf(cm0, __shfl_xor_sync(0xffffffffu, cm0, 2));
            cm1 = fmaxf(cm1, __shfl_xor_sync(0xffffffffu, cm1, 1));
            cm1 = fmaxf(cm1, __shfl_xor_sync(0xffffffffu, cm1, 2));

            const float mn0 = fmaxf(m0, cm0);
            const float mn1 = fmaxf(m1, cm1);
            const float sc0 = __expf(m0 - mn0);   // exp(-inf)=0 first time
            const float sc1 = __expf(m1 - mn1);
            m0 = mn0; m1 = mn1;
            l0 *= sc0; l1 *= sc1;
#pragma unroll
            for (int nt = 0; nt < 8; nt++) {
                Oa[nt][0] *= sc0; Oa[nt][1] *= sc0;
                Oa[nt][2] *= sc1; Oa[nt][3] *= sc1;
            }

            // ---- p = exp(s - m), partial row sums
            float ps0 = 0.f, ps1 = 0.f;
#pragma unroll
            for (int nt = 0; nt < 8; nt++) {
                float p0 = __expf(Sa[nt][0] - m0);
                float p1 = __expf(Sa[nt][1] - m0);
                float p2 = __expf(Sa[nt][2] - m1);
                float p3 = __expf(Sa[nt][3] - m1);
                Sa[nt][0] = p0; Sa[nt][1] = p1; Sa[nt][2] = p2; Sa[nt][3] = p3;
                ps0 += p0 + p1; ps1 += p2 + p3;
            }
            l0 += ps0; l1 += ps1;

            // ---- O += P V (bf16x3), P frags packed from S accumulators
#pragma unroll
            for (int c = 0; c < 4; c++) {
                unsigned ph0, pl0, ph1, pl1, ph2, pl2, ph3, pl3;
                split2(Sa[2 * c][0],     Sa[2 * c][1],     ph0, pl0);
                split2(Sa[2 * c][2],     Sa[2 * c][3],     ph1, pl1);
                split2(Sa[2 * c + 1][0], Sa[2 * c + 1][1], ph2, pl2);
                split2(Sa[2 * c + 1][2], Sa[2 * c + 1][3], ph3, pl3);
#pragma unroll
                for (int nt = 0; nt < 8; nt++) {
                    const int rb = nt * 8 + gid;
                    const int gb = ctid ^ ((rb ^ (rb >> 2)) & 3);
                    float4 vv = *(const float4*)&Vs[c][rb][gb << 2];
                    const unsigned vh0 = __float_as_uint(vv.x);
                    const unsigned vh1 = __float_as_uint(vv.y);
                    const unsigned vl0 = __float_as_uint(vv.z);
                    const unsigned vl1 = __float_as_uint(vv.w);
                    mma_bf16(Oa[nt], ph0, ph1, ph2, ph3, vh0, vh1);
                    mma_bf16(Oa[nt], pl0, pl1, pl2, pl3, vh0, vh1);
                    mma_bf16(Oa[nt], ph0, ph1, ph2, ph3, vl0, vl1);
                }
            }
        }
        __syncthreads();
    }

    // ---- finalize: reduce l across quad, normalize, store
    l0 += __shfl_xor_sync(0xffffffffu, l0, 1);
    l0 += __shfl_xor_sync(0xffffffffu, l0, 2);
    l1 += __shfl_xor_sync(0xffffffffu, l1, 1);
    l1 += __shfl_xor_sync(0xffffffffu, l1, 2);
    const float inv0 = 1.f / l0;
    const float inv1 = 1.f / l1;

    float* y0 = y + (long)(b * T_ + qr0) * C_ + h * HS;
    float* y1 = y + (long)(b * T_ + qr1) * C_ + h * HS;
#pragma unroll
    for (int nt = 0; nt < 8; nt++) {
        const int cc = nt * 8 + 2 * ctid;
        *(float2*)(y0 + cc) = make_float2(Oa[nt][0] * inv0, Oa[nt][1] * inv0);
        *(float2*)(y1 + cc) = make_float2(Oa[nt][2] * inv1, Oa[nt][3] * inv1);
    }
}

// ---------------------------------------------------------------------------
extern "C" void kernel_launch(void* const* d_in, const int* in_sizes, int n_in,
                              void* d_out, int out_size)
{
    const float* x    = (const float*)d_in[0];
    const float* watt = (const float*)d_in[1];
    const float* wprj = (const float*)d_in[2];
    float* out = (float*)d_out;

    float *qkv, *y;
    cudaGetSymbolAddress((void**)&qkv, g_qkv);
    cudaGetSymbolAddress((void**)&y,   g_y);

    dim3 g1(C3 / 128, (B_ * T_) / 128);
    bf16x3_gemm_nt<<<g1, 256>>>(x, watt, qkv, B_ * T_, C3, C_);

    dim3 g2(T_ / 128, NH, B_);
    attn_mma<<<g2, 256>>>(qkv, y);

    dim3 g3(C_ / 128, (B_ * T_) / 128);
    bf16x3_gemm_nt<<<g3, 256>>>(y, wprj, out, B_ * T_, C_, C_);
}

// round 10
// speedup vs baseline: 2.4210x; 1.0480x over previous
#include <cuda_runtime.h>
#include <math.h>

// Problem constants
#define B_  4
#define T_  2048
#define C_  1024
#define NH  16
#define HS  64
#define C3  3072   // 3*C

// Scratch (no allocations allowed)
__device__ float g_qkv[B_ * T_ * C3];
__device__ float g_y[B_ * T_ * C_];

// ---------------------------------------------------------------------------
// bf16x3 helpers (validated R6/R7)
// ---------------------------------------------------------------------------
__device__ __forceinline__ void bf16x3_store_pair(
    float* __restrict__ S, int row, int swz, int jp, float x0, float x1)
{
    const unsigned w0 = __float_as_uint(x0);
    const unsigned w1 = __float_as_uint(x1);
    const unsigned hw = (w0 >> 16) | (w1 & 0xffff0000u);
    const float r0 = x0 - __uint_as_float(w0 & 0xffff0000u);   // exact
    const float r1 = x1 - __uint_as_float(w1 & 0xffff0000u);   // exact
    unsigned lw;
    asm("cvt.rn.bf16x2.f32 %0, %1, %2;" : "=r"(lw) : "f"(r1), "f"(r0));
    const int base = row * 16 + (((jp & 3) ^ swz) << 2) + (jp >> 2);
    S[base]     = __uint_as_float(hw);
    S[base + 2] = __uint_as_float(lw);
}

__device__ __forceinline__ void split2(float x0, float x1, unsigned& hw, unsigned& lw)
{
    const unsigned w0 = __float_as_uint(x0);
    const unsigned w1 = __float_as_uint(x1);
    hw = (w0 >> 16) | (w1 & 0xffff0000u);
    const float r0 = x0 - __uint_as_float(w0 & 0xffff0000u);
    const float r1 = x1 - __uint_as_float(w1 & 0xffff0000u);
    asm("cvt.rn.bf16x2.f32 %0, %1, %2;" : "=r"(lw) : "f"(r1), "f"(r0));
}

__device__ __forceinline__ void mma_bf16(
    float* d, unsigned a0, unsigned a1, unsigned a2, unsigned a3,
    unsigned b0, unsigned b1)
{
    asm volatile(
        "mma.sync.aligned.m16n8k16.row.col.f32.bf16.bf16.f32 "
        "{%0,%1,%2,%3}, {%4,%5,%6,%7}, {%8,%9}, {%0,%1,%2,%3};\n"
        : "+f"(d[0]), "+f"(d[1]), "+f"(d[2]), "+f"(d[3])
        : "r"(a0), "r"(a1), "r"(a2), "r"(a3), "r"(b0), "r"(b1));
}

// ---------------------------------------------------------------------------
// bf16x3 split GEMM, v2: 2-stage SMEM double buffer, ONE __syncthreads per
// k-stage. iter s: store tile s -> buf[s&1]; sync; LDG tile s+1 (overlaps
// mma); fragments+mma from buf[s&1].
// ---------------------------------------------------------------------------
__global__ __launch_bounds__(256) void bf16x3_gemm_nt(
    const float* __restrict__ A, const float* __restrict__ Bm,
    float* __restrict__ Cm, int M, int N, int K)
{
    __shared__ float As[2][128 * 16];
    __shared__ float Bs[2][128 * 16];

    const int tid  = threadIdx.x;
    const int lane = tid & 31;
    const int warp = tid >> 5;
    const int wm   = (warp >> 2) * 64;
    const int wn   = (warp & 3) * 32;
    const int gid  = lane >> 2;
    const int ctid = lane & 3;

    const int m0 = blockIdx.y * 128;
    const int n0 = blockIdx.x * 128;

    const int lrow = tid >> 1;
    const int lq0  = (tid & 1) * 2;
    const int swzs = (lrow ^ (lrow >> 2)) & 3;

    const float* Ag = A  + (long)(m0 + lrow) * K + lq0 * 4;
    const float* Bg = Bm + (long)(n0 + lrow) * K + lq0 * 4;

    float acc[4][4][4];
#pragma unroll
    for (int i = 0; i < 4; i++)
#pragma unroll
        for (int j = 0; j < 4; j++)
#pragma unroll
            for (int r = 0; r < 4; r++) acc[i][j][r] = 0.f;

    const int nstages = K / 16;

    float4 pa0 = *(const float4*)(Ag);
    float4 pa1 = *(const float4*)(Ag + 4);
    float4 pb0 = *(const float4*)(Bg);
    float4 pb1 = *(const float4*)(Bg + 4);

    for (int s = 0; s < nstages; s++) {
        float* Ab = As[s & 1];
        float* Bb = Bs[s & 1];
        // store tile s (in regs) into buf[s&1]
        bf16x3_store_pair(Ab, lrow, swzs, 2 * lq0 + 0, pa0.x, pa0.y);
        bf16x3_store_pair(Ab, lrow, swzs, 2 * lq0 + 1, pa0.z, pa0.w);
        bf16x3_store_pair(Ab, lrow, swzs, 2 * lq0 + 2, pa1.x, pa1.y);
        bf16x3_store_pair(Ab, lrow, swzs, 2 * lq0 + 3, pa1.z, pa1.w);
        bf16x3_store_pair(Bb, lrow, swzs, 2 * lq0 + 0, pb0.x, pb0.y);
        bf16x3_store_pair(Bb, lrow, swzs, 2 * lq0 + 1, pb0.z, pb0.w);
        bf16x3_store_pair(Bb, lrow, swzs, 2 * lq0 + 2, pb1.x, pb1.y);
        bf16x3_store_pair(Bb, lrow, swzs, 2 * lq0 + 3, pb1.z, pb1.w);
        __syncthreads();

        // prefetch tile s+1 (clamped on last iter; values unused) — LDG
        // latency overlaps the mma block below
        {
            const long off = (s + 1 < nstages) ? (long)(s + 1) * 16 : 0;
            pa0 = *(const float4*)(Ag + off);
            pa1 = *(const float4*)(Ag + off + 4);
            pb0 = *(const float4*)(Bg + off);
            pb1 = *(const float4*)(Bg + off + 4);
        }

        // fragments + mma from buf[s&1]
        float4 af[4][2];
        float4 bf[4];
#pragma unroll
        for (int mt = 0; mt < 4; mt++) {
            const int r0 = wm + mt * 16 + gid;
            const int r1 = r0 + 8;
            const int g0 = ctid ^ ((r0 ^ (r0 >> 2)) & 3);
            const int g1 = ctid ^ ((r1 ^ (r1 >> 2)) & 3);
            af[mt][0] = *(const float4*)&Ab[r0 * 16 + (g0 << 2)];
            af[mt][1] = *(const float4*)&Ab[r1 * 16 + (g1 << 2)];
        }
#pragma unroll
        for (int nt = 0; nt < 4; nt++) {
            const int rb = wn + nt * 8 + gid;
            const int gb = ctid ^ ((rb ^ (rb >> 2)) & 3);
            bf[nt] = *(const float4*)&Bb[rb * 16 + (gb << 2)];
        }

#pragma unroll
        for (int mt = 0; mt < 4; mt++) {
            const unsigned ah0 = __float_as_uint(af[mt][0].x);
            const unsigned ah1 = __float_as_uint(af[mt][1].x);
            const unsigned ah2 = __float_as_uint(af[mt][0].y);
            const unsigned ah3 = __float_as_uint(af[mt][1].y);
            const unsigned al0 = __float_as_uint(af[mt][0].z);
            const unsigned al1 = __float_as_uint(af[mt][1].z);
            const unsigned al2 = __float_as_uint(af[mt][0].w);
            const unsigned al3 = __float_as_uint(af[mt][1].w);
#pragma unroll
            for (int nt = 0; nt < 4; nt++) {
                float* d = acc[mt][nt];
                const unsigned bh0 = __float_as_uint(bf[nt].x);
                const unsigned bh1 = __float_as_uint(bf[nt].y);
                const unsigned bl0 = __float_as_uint(bf[nt].z);
                const unsigned bl1 = __float_as_uint(bf[nt].w);
                mma_bf16(d, ah0, ah1, ah2, ah3, bh0, bh1);
                mma_bf16(d, al0, al1, al2, al3, bh0, bh1);
                mma_bf16(d, ah0, ah1, ah2, ah3, bl0, bl1);
            }
        }
    }

#pragma unroll
    for (int mt = 0; mt < 4; mt++) {
        const int r0 = m0 + wm + mt * 16 + gid;
#pragma unroll
        for (int nt = 0; nt < 4; nt++) {
            const int c = n0 + wn + nt * 8 + 2 * ctid;
            *(float2*)(Cm + (long)r0 * N + c)       = make_float2(acc[mt][nt][0], acc[mt][nt][1]);
            *(float2*)(Cm + (long)(r0 + 8) * N + c) = make_float2(acc[mt][nt][2], acc[mt][nt][3]);
        }
    }
}

// ---------------------------------------------------------------------------
// bf16x3 tensor-core flash attention (unchanged from R7; validated 6.1e-5)
// ---------------------------------------------------------------------------
__global__ __launch_bounds__(256) void attn_mma(
    const float* __restrict__ qkv, float* __restrict__ y)
{
    __shared__ float Ks[4][64][16];
    __shared__ float Vs[4][64][16];

    const int qt   = (int)gridDim.x - 1 - (int)blockIdx.x;
    const int h    = blockIdx.y;
    const int b    = blockIdx.z;
    const int tid  = threadIdx.x;
    const int lane = tid & 31;
    const int warp = tid >> 5;
    const int gid  = lane >> 2;
    const int ctid = lane & 3;
    const int qbase = qt * 128 + warp * 16;
    const int qr0 = qbase + gid;
    const int qr1 = qr0 + 8;

    const float* base = qkv + (long)b * T_ * C3;

    unsigned qh[4][4], ql[4][4];
#pragma unroll
    for (int c = 0; c < 4; c++) {
        const float* q0p = base + (long)qr0 * C3 + h * HS + c * 16;
        const float* q1p = base + (long)qr1 * C3 + h * HS + c * 16;
        float2 x00 = *(const float2*)(q0p + 2 * ctid);
        float2 x10 = *(const float2*)(q1p + 2 * ctid);
        float2 x01 = *(const float2*)(q0p + 8 + 2 * ctid);
        float2 x11 = *(const float2*)(q1p + 8 + 2 * ctid);
        split2(x00.x, x00.y, qh[c][0], ql[c][0]);
        split2(x10.x, x10.y, qh[c][1], ql[c][1]);
        split2(x01.x, x01.y, qh[c][2], ql[c][2]);
        split2(x11.x, x11.y, qh[c][3], ql[c][3]);
    }

    float Oa[8][4];
#pragma unroll
    for (int nt = 0; nt < 8; nt++)
#pragma unroll
        for (int r = 0; r < 4; r++) Oa[nt][r] = 0.f;
    float m0 = -INFINITY, m1 = -INFINITY, l0 = 0.f, l1 = 0.f;

    const int krow = tid >> 2;
    const int kch  = tid & 3;
    const int kswz = (krow ^ (krow >> 2)) & 3;
    const int vkp  = tid >> 3;
    const int hpz  = tid & 7;
    const int vck  = vkp >> 3;
    const int vjp  = vkp & 7;

    const int ntiles = 2 * qt + 2;

    for (int kt = 0; kt < ntiles; kt++) {
        {
            const float* kg = base + (long)(kt * 64 + krow) * C3 + C_ + h * HS + kch * 16;
            float4 f0 = *(const float4*)(kg);
            float4 f1 = *(const float4*)(kg + 4);
            float4 f2 = *(const float4*)(kg + 8);
            float4 f3 = *(const float4*)(kg + 12);
            float* Sc = &Ks[kch][0][0];
            bf16x3_store_pair(Sc, krow, kswz, 0, f0.x, f0.y);
            bf16x3_store_pair(Sc, krow, kswz, 1, f0.z, f0.w);
            bf16x3_store_pair(Sc, krow, kswz, 2, f1.x, f1.y);
            bf16x3_store_pair(Sc, krow, kswz, 3, f1.z, f1.w);
            bf16x3_store_pair(Sc, krow, kswz, 4, f2.x, f2.y);
            bf16x3_store_pair(Sc, krow, kswz, 5, f2.z, f2.w);
            bf16x3_store_pair(Sc, krow, kswz, 6, f3.x, f3.y);
            bf16x3_store_pair(Sc, krow, kswz, 7, f3.z, f3.w);
        }
        {
            const float* v0g = base + (long)(kt * 64 + 2 * vkp) * C3 + 2 * C_ + h * HS;
            const float* v1g = v0g + C3;
            float* Sv = &Vs[vck][0][0];
#pragma unroll
            for (int i = 0; i < 4; i++) {
                const int hh = 2 * (hpz + 8 * i);
                float2 v0 = *(const float2*)(v0g + hh);
                float2 v1 = *(const float2*)(v1g + hh);
                const int sw0 = (hh ^ (hh >> 2)) & 3;
                const int sw1 = ((hh + 1) ^ ((hh + 1) >> 2)) & 3;
                bf16x3_store_pair(Sv, hh,     sw0, vjp, v0.x, v1.x);
                bf16x3_store_pair(Sv, hh + 1, sw1, vjp, v0.y, v1.y);
            }
        }
        __syncthreads();

        if (qbase + 15 >= kt * 64) {
            float Sa[8][4];
#pragma unroll
            for (int nt = 0; nt < 8; nt++)
#pragma unroll
                for (int r = 0; r < 4; r++) Sa[nt][r] = 0.f;
#pragma unroll
            for (int nt = 0; nt < 8; nt++) {
                const int rb = nt * 8 + gid;
                const int gb = ctid ^ ((rb ^ (rb >> 2)) & 3);
#pragma unroll
                for (int c = 0; c < 4; c++) {
                    float4 bv = *(const float4*)&Ks[c][rb][gb << 2];
                    const unsigned bh0 = __float_as_uint(bv.x);
                    const unsigned bh1 = __float_as_uint(bv.y);
                    const unsigned bl0 = __float_as_uint(bv.z);
                    const unsigned bl1 = __float_as_uint(bv.w);
                    mma_bf16(Sa[nt], qh[c][0], qh[c][1], qh[c][2], qh[c][3], bh0, bh1);
                    mma_bf16(Sa[nt], ql[c][0], ql[c][1], ql[c][2], ql[c][3], bh0, bh1);
                    mma_bf16(Sa[nt], qh[c][0], qh[c][1], qh[c][2], qh[c][3], bl0, bl1);
                }
            }

            const bool need_mask = (kt >= 2 * qt);
#pragma unroll
            for (int nt = 0; nt < 8; nt++) {
                const int col = kt * 64 + nt * 8 + 2 * ctid;
                Sa[nt][0] *= 0.125f; Sa[nt][1] *= 0.125f;
                Sa[nt][2] *= 0.125f; Sa[nt][3] *= 0.125f;
                if (need_mask) {
                    if (col     > qr0) Sa[nt][0] = -INFINITY;
                    if (col + 1 > qr0) Sa[nt][1] = -INFINITY;
                    if (col     > qr1) Sa[nt][2] = -INFINITY;
                    if (col + 1 > qr1) Sa[nt][3] = -INFINITY;
                }
            }

            float cm0 = -INFINITY, cm1 = -INFINITY;
#pragma unroll
            for (int nt = 0; nt < 8; nt++) {
                cm0 = fmaxf(cm0, fmaxf(Sa[nt][0], Sa[nt][1]));
                cm1 = fmaxf(cm1, fmaxf(Sa[nt][2], Sa[nt][3]));
            }
            cm0 = fmaxf(cm0, __shfl_xor_sync(0xffffffffu, cm0, 1));
            cm0 = fmaxf(cm0, __shfl_xor_sync(0xffffffffu, cm0, 2));
            cm1 = fmaxf(cm1, __shfl_xor_sync(0xffffffffu, cm1, 1));
            cm1 = fmaxf(cm1, __shfl_xor_sync(0xffffffffu, cm1, 2));

            const float mn0 = fmaxf(m0, cm0);
            const float mn1 = fmaxf(m1, cm1);
            const float sc0 = __expf(m0 - mn0);
            const float sc1 = __expf(m1 - mn1);
            m0 = mn0; m1 = mn1;
            l0 *= sc0; l1 *= sc1;
#pragma unroll
            for (int nt = 0; nt < 8; nt++) {
                Oa[nt][0] *= sc0; Oa[nt][1] *= sc0;
                Oa[nt][2] *= sc1; Oa[nt][3] *= sc1;
            }

            float ps0 = 0.f, ps1 = 0.f;
#pragma unroll
            for (int nt = 0; nt < 8; nt++) {
                float p0 = __expf(Sa[nt][0] - m0);
                float p1 = __expf(Sa[nt][1] - m0);
                float p2 = __expf(Sa[nt][2] - m1);
                float p3 = __expf(Sa[nt][3] - m1);
                Sa[nt][0] = p0; Sa[nt][1] = p1; Sa[nt][2] = p2; Sa[nt][3] = p3;
                ps0 += p0 + p1; ps1 += p2 + p3;
            }
            l0 += ps0; l1 += ps1;

#pragma unroll
            for (int c = 0; c < 4; c++) {
                unsigned ph0, pl0, ph1, pl1, ph2, pl2, ph3, pl3;
                split2(Sa[2 * c][0],     Sa[2 * c][1],     ph0, pl0);
                split2(Sa[2 * c][2],     Sa[2 * c][3],     ph1, pl1);
                split2(Sa[2 * c + 1][0], Sa[2 * c + 1][1], ph2, pl2);
                split2(Sa[2 * c + 1][2], Sa[2 * c + 1][3], ph3, pl3);
#pragma unroll
                for (int nt = 0; nt < 8; nt++) {
                    const int rb = nt * 8 + gid;
                    const int gb = ctid ^ ((rb ^ (rb >> 2)) & 3);
                    float4 vv = *(const float4*)&Vs[c][rb][gb << 2];
                    const unsigned vh0 = __float_as_uint(vv.x);
                    const unsigned vh1 = __float_as_uint(vv.y);
                    const unsigned vl0 = __float_as_uint(vv.z);
                    const unsigned vl1 = __float_as_uint(vv.w);
                    mma_bf16(Oa[nt], ph0, ph1, ph2, ph3, vh0, vh1);
                    mma_bf16(Oa[nt], pl0, pl1, pl2, pl3, vh0, vh1);
                    mma_bf16(Oa[nt], ph0, ph1, ph2, ph3, vl0, vl1);
                }
            }
        }
        __syncthreads();
    }

    l0 += __shfl_xor_sync(0xffffffffu, l0, 1);
    l0 += __shfl_xor_sync(0xffffffffu, l0, 2);
    l1 += __shfl_xor_sync(0xffffffffu, l1, 1);
    l1 += __shfl_xor_sync(0xffffffffu, l1, 2);
    const float inv0 = 1.f / l0;
    const float inv1 = 1.f / l1;

    float* y0 = y + (long)(b * T_ + qr0) * C_ + h * HS;
    float* y1 = y + (long)(b * T_ + qr1) * C_ + h * HS;
#pragma unroll
    for (int nt = 0; nt < 8; nt++) {
        const int cc = nt * 8 + 2 * ctid;
        *(float2*)(y0 + cc) = make_float2(Oa[nt][0] * inv0, Oa[nt][1] * inv0);
        *(float2*)(y1 + cc) = make_float2(Oa[nt][2] * inv1, Oa[nt][3] * inv1);
    }
}

// ---------------------------------------------------------------------------
extern "C" void kernel_launch(void* const* d_in, const int* in_sizes, int n_in,
                              void* d_out, int out_size)
{
    const float* x    = (const float*)d_in[0];
    const float* watt = (const float*)d_in[1];
    const float* wprj = (const float*)d_in[2];
    float* out = (float*)d_out;

    float *qkv, *y;
    cudaGetSymbolAddress((void**)&qkv, g_qkv);
    cudaGetSymbolAddress((void**)&y,   g_y);

    dim3 g1(C3 / 128, (B_ * T_) / 128);
    bf16x3_gemm_nt<<<g1, 256>>>(x, watt, qkv, B_ * T_, C3, C_);

    dim3 g2(T_ / 128, NH, B_);
    attn_mma<<<g2, 256>>>(qkv, y);

    dim3 g3(C_ / 128, (B_ * T_) / 128);
    bf16x3_gemm_nt<<<g3, 256>>>(y, wprj, out, B_ * T_, C_, C_);
}

// round 11
// speedup vs baseline: 2.8676x; 1.1845x over previous
#include <cuda_runtime.h>
#include <math.h>

// Problem constants
#define B_  4
#define T_  2048
#define C_  1024
#define NH  16
#define HS  64
#define C3  3072   // 3*C

// Scratch (no allocations allowed)
__device__ float    g_qkv[B_ * T_ * C3];
__device__ float    g_y[B_ * T_ * C_];
__device__ unsigned g_xp[B_ * T_ * C_];     // packed x
__device__ unsigned g_wattp[C3 * C_];       // packed w_attn
__device__ unsigned g_wprjp[C_ * C_];       // packed w_proj
__device__ unsigned g_yp[B_ * T_ * C_];     // packed y

// ---------------------------------------------------------------------------
// bf16x3 helpers (validated R6/R7)
// ---------------------------------------------------------------------------
__device__ __forceinline__ void bf16x3_store_pair(
    float* __restrict__ S, int row, int swz, int jp, float x0, float x1)
{
    const unsigned w0 = __float_as_uint(x0);
    const unsigned w1 = __float_as_uint(x1);
    const unsigned hw = (w0 >> 16) | (w1 & 0xffff0000u);
    const float r0 = x0 - __uint_as_float(w0 & 0xffff0000u);   // exact
    const float r1 = x1 - __uint_as_float(w1 & 0xffff0000u);   // exact
    unsigned lw;
    asm("cvt.rn.bf16x2.f32 %0, %1, %2;" : "=r"(lw) : "f"(r1), "f"(r0));
    const int base = row * 16 + (((jp & 3) ^ swz) << 2) + (jp >> 2);
    S[base]     = __uint_as_float(hw);
    S[base + 2] = __uint_as_float(lw);
}

__device__ __forceinline__ void split2(float x0, float x1, unsigned& hw, unsigned& lw)
{
    const unsigned w0 = __float_as_uint(x0);
    const unsigned w1 = __float_as_uint(x1);
    hw = (w0 >> 16) | (w1 & 0xffff0000u);
    const float r0 = x0 - __uint_as_float(w0 & 0xffff0000u);
    const float r1 = x1 - __uint_as_float(w1 & 0xffff0000u);
    asm("cvt.rn.bf16x2.f32 %0, %1, %2;" : "=r"(lw) : "f"(r1), "f"(r0));
}

__device__ __forceinline__ void mma_bf16(
    float* d, unsigned a0, unsigned a1, unsigned a2, unsigned a3,
    unsigned b0, unsigned b1)
{
    asm volatile(
        "mma.sync.aligned.m16n8k16.row.col.f32.bf16.bf16.f32 "
        "{%0,%1,%2,%3}, {%4,%5,%6,%7}, {%8,%9}, {%0,%1,%2,%3};\n"
        : "+f"(d[0]), "+f"(d[1]), "+f"(d[2]), "+f"(d[3])
        : "r"(a0), "r"(a1), "r"(a2), "r"(a3), "r"(b0), "r"(b1));
}

__device__ __forceinline__ void cp16(unsigned smem_addr, const void* gptr)
{
    asm volatile("cp.async.cg.shared.global [%0], [%1], 16;"
                 :: "r"(smem_addr), "l"(gptr));
}

// ---------------------------------------------------------------------------
// Pack kernel: fp32 row-major [rows, K] -> per-row 16-word chunks holding the
// bf16x3 hi/lo words in the EXACT swizzled smem layout (swz from row&127, the
// same for every 128-row tile). One thread = one (row, chunk of 16 k).
// ---------------------------------------------------------------------------
__global__ __launch_bounds__(256) void pack_bf16x3(
    const float* __restrict__ in, unsigned* __restrict__ out, int total, int K)
{
    const int idx = blockIdx.x * 256 + threadIdx.x;
    if (idx >= total) return;
    const int nck = K / 16;
    const int row = idx / nck;
    const int c   = idx % nck;
    const int r   = row & 127;
    const int swz = (r ^ (r >> 2)) & 3;

    const float* p = in + (long)row * K + c * 16;
    unsigned w[16];
#pragma unroll
    for (int j = 0; j < 8; j++) {
        unsigned hw, lw;
        split2(p[2 * j], p[2 * j + 1], hw, lw);
        const int pos = (((j & 3) ^ swz) << 2) + (j >> 2);
        w[pos]     = hw;
        w[pos + 2] = lw;
    }
    uint4* o = (uint4*)(out + (long)row * K + c * 16);
    o[0] = make_uint4(w[0],  w[1],  w[2],  w[3]);
    o[1] = make_uint4(w[4],  w[5],  w[6],  w[7]);
    o[2] = make_uint4(w[8],  w[9],  w[10], w[11]);
    o[3] = make_uint4(w[12], w[13], w[14], w[15]);
}

// ---------------------------------------------------------------------------
// Packed GEMM: C[M,N] = A*B^T from pre-packed operands. cp.async 3-stage ring,
// one barrier per stage, zero in-loop conversion. 2 CTAs/SM.
// ---------------------------------------------------------------------------
__global__ __launch_bounds__(256, 2) void gemm_packed(
    const unsigned* __restrict__ Ap, const unsigned* __restrict__ Bp,
    float* __restrict__ Cm, int M, int N, int K)
{
    __shared__ unsigned As[3][2048];   // 3 x 8KB
    __shared__ unsigned Bs[3][2048];   // 3 x 8KB  (total 48KB)

    const int tid  = threadIdx.x;
    const int lane = tid & 31;
    const int warp = tid >> 5;
    const int wm   = (warp >> 2) * 64;
    const int wn   = (warp & 3) * 32;
    const int gid  = lane >> 2;
    const int ctid = lane & 3;

    const int m0 = blockIdx.y * 128;
    const int n0 = blockIdx.x * 128;

    const int lrow = tid >> 1;
    const int half = tid & 1;

    const unsigned* Ag = Ap + (long)(m0 + lrow) * K + half * 8;
    const unsigned* Bg = Bp + (long)(n0 + lrow) * K + half * 8;

    const unsigned aBase = (unsigned)__cvta_generic_to_shared(&As[0][0]);
    const unsigned bBase = (unsigned)__cvta_generic_to_shared(&Bs[0][0]);
    const unsigned doff  = (unsigned)(lrow * 16 + half * 8) * 4u;

    float acc[4][4][4];
#pragma unroll
    for (int i = 0; i < 4; i++)
#pragma unroll
        for (int j = 0; j < 4; j++)
#pragma unroll
            for (int r = 0; r < 4; r++) acc[i][j][r] = 0.f;

    const int nstages = K / 16;

#define GP_ISSUE(st) do {                                              \
        const unsigned bufb = ((st) % 3) * 8192u;                      \
        cp16(aBase + bufb + doff,      Ag + (st) * 16);                \
        cp16(aBase + bufb + doff + 16, Ag + (st) * 16 + 4);            \
        cp16(bBase + bufb + doff,      Bg + (st) * 16);                \
        cp16(bBase + bufb + doff + 16, Bg + (st) * 16 + 4);            \
    } while (0)

    GP_ISSUE(0);
    asm volatile("cp.async.commit_group;" ::: "memory");
    GP_ISSUE(1);
    asm volatile("cp.async.commit_group;" ::: "memory");

    int buf = 0;
    for (int s = 0; s < nstages; s++) {
        asm volatile("cp.async.wait_group 1;" ::: "memory");
        __syncthreads();
        if (s + 2 < nstages) GP_ISSUE(s + 2);
        asm volatile("cp.async.commit_group;" ::: "memory");

        const unsigned* Ab = As[buf];
        const unsigned* Bb = Bs[buf];
        buf = (buf == 2) ? 0 : buf + 1;

        uint4 af[4][2];
        uint4 bf[4];
#pragma unroll
        for (int mt = 0; mt < 4; mt++) {
            const int r0 = wm + mt * 16 + gid;
            const int r1 = r0 + 8;
            const int g0 = ctid ^ ((r0 ^ (r0 >> 2)) & 3);
            const int g1 = ctid ^ ((r1 ^ (r1 >> 2)) & 3);
            af[mt][0] = *(const uint4*)&Ab[r0 * 16 + (g0 << 2)];
            af[mt][1] = *(const uint4*)&Ab[r1 * 16 + (g1 << 2)];
        }
#pragma unroll
        for (int nt = 0; nt < 4; nt++) {
            const int rb = wn + nt * 8 + gid;
            const int gb = ctid ^ ((rb ^ (rb >> 2)) & 3);
            bf[nt] = *(const uint4*)&Bs[0][0 + (buf == 0 ? 2 : buf - 1) * 0];
            bf[nt] = *(const uint4*)&Bb[rb * 16 + (gb << 2)];
        }

#pragma unroll
        for (int mt = 0; mt < 4; mt++) {
            const unsigned ah0 = af[mt][0].x, ah1 = af[mt][1].x;
            const unsigned ah2 = af[mt][0].y, ah3 = af[mt][1].y;
            const unsigned al0 = af[mt][0].z, al1 = af[mt][1].z;
            const unsigned al2 = af[mt][0].w, al3 = af[mt][1].w;
#pragma unroll
            for (int nt = 0; nt < 4; nt++) {
                float* d = acc[mt][nt];
                mma_bf16(d, ah0, ah1, ah2, ah3, bf[nt].x, bf[nt].y);   // Ah*Bh
                mma_bf16(d, al0, al1, al2, al3, bf[nt].x, bf[nt].y);   // Al*Bh
                mma_bf16(d, ah0, ah1, ah2, ah3, bf[nt].z, bf[nt].w);   // Ah*Bl
            }
        }
    }
#undef GP_ISSUE

#pragma unroll
    for (int mt = 0; mt < 4; mt++) {
        const int r0 = m0 + wm + mt * 16 + gid;
#pragma unroll
        for (int nt = 0; nt < 4; nt++) {
            const int c = n0 + wn + nt * 8 + 2 * ctid;
            *(float2*)(Cm + (long)r0 * N + c)       = make_float2(acc[mt][nt][0], acc[mt][nt][1]);
            *(float2*)(Cm + (long)(r0 + 8) * N + c) = make_float2(acc[mt][nt][2], acc[mt][nt][3]);
        }
    }
}

// ---------------------------------------------------------------------------
// bf16x3 tensor-core flash attention (unchanged from R7; validated 6.1e-5)
// ---------------------------------------------------------------------------
__global__ __launch_bounds__(256) void attn_mma(
    const float* __restrict__ qkv, float* __restrict__ y)
{
    __shared__ float Ks[4][64][16];
    __shared__ float Vs[4][64][16];

    const int qt   = (int)gridDim.x - 1 - (int)blockIdx.x;
    const int h    = blockIdx.y;
    const int b    = blockIdx.z;
    const int tid  = threadIdx.x;
    const int lane = tid & 31;
    const int warp = tid >> 5;
    const int gid  = lane >> 2;
    const int ctid = lane & 3;
    const int qbase = qt * 128 + warp * 16;
    const int qr0 = qbase + gid;
    const int qr1 = qr0 + 8;

    const float* base = qkv + (long)b * T_ * C3;

    unsigned qh[4][4], ql[4][4];
#pragma unroll
    for (int c = 0; c < 4; c++) {
        const float* q0p = base + (long)qr0 * C3 + h * HS + c * 16;
        const float* q1p = base + (long)qr1 * C3 + h * HS + c * 16;
        float2 x00 = *(const float2*)(q0p + 2 * ctid);
        float2 x10 = *(const float2*)(q1p + 2 * ctid);
        float2 x01 = *(const float2*)(q0p + 8 + 2 * ctid);
        float2 x11 = *(const float2*)(q1p + 8 + 2 * ctid);
        split2(x00.x, x00.y, qh[c][0], ql[c][0]);
        split2(x10.x, x10.y, qh[c][1], ql[c][1]);
        split2(x01.x, x01.y, qh[c][2], ql[c][2]);
        split2(x11.x, x11.y, qh[c][3], ql[c][3]);
    }

    float Oa[8][4];
#pragma unroll
    for (int nt = 0; nt < 8; nt++)
#pragma unroll
        for (int r = 0; r < 4; r++) Oa[nt][r] = 0.f;
    float m0 = -INFINITY, m1 = -INFINITY, l0 = 0.f, l1 = 0.f;

    const int krow = tid >> 2;
    const int kch  = tid & 3;
    const int kswz = (krow ^ (krow >> 2)) & 3;
    const int vkp  = tid >> 3;
    const int hpz  = tid & 7;
    const int vck  = vkp >> 3;
    const int vjp  = vkp & 7;

    const int ntiles = 2 * qt + 2;

    for (int kt = 0; kt < ntiles; kt++) {
        {
            const float* kg = base + (long)(kt * 64 + krow) * C3 + C_ + h * HS + kch * 16;
            float4 f0 = *(const float4*)(kg);
            float4 f1 = *(const float4*)(kg + 4);
            float4 f2 = *(const float4*)(kg + 8);
            float4 f3 = *(const float4*)(kg + 12);
            float* Sc = &Ks[kch][0][0];
            bf16x3_store_pair(Sc, krow, kswz, 0, f0.x, f0.y);
            bf16x3_store_pair(Sc, krow, kswz, 1, f0.z, f0.w);
            bf16x3_store_pair(Sc, krow, kswz, 2, f1.x, f1.y);
            bf16x3_store_pair(Sc, krow, kswz, 3, f1.z, f1.w);
            bf16x3_store_pair(Sc, krow, kswz, 4, f2.x, f2.y);
            bf16x3_store_pair(Sc, krow, kswz, 5, f2.z, f2.w);
            bf16x3_store_pair(Sc, krow, kswz, 6, f3.x, f3.y);
            bf16x3_store_pair(Sc, krow, kswz, 7, f3.z, f3.w);
        }
        {
            const float* v0g = base + (long)(kt * 64 + 2 * vkp) * C3 + 2 * C_ + h * HS;
            const float* v1g = v0g + C3;
            float* Sv = &Vs[vck][0][0];
#pragma unroll
            for (int i = 0; i < 4; i++) {
                const int hh = 2 * (hpz + 8 * i);
                float2 v0 = *(const float2*)(v0g + hh);
                float2 v1 = *(const float2*)(v1g + hh);
                const int sw0 = (hh ^ (hh >> 2)) & 3;
                const int sw1 = ((hh + 1) ^ ((hh + 1) >> 2)) & 3;
                bf16x3_store_pair(Sv, hh,     sw0, vjp, v0.x, v1.x);
                bf16x3_store_pair(Sv, hh + 1, sw1, vjp, v0.y, v1.y);
            }
        }
        __syncthreads();

        if (qbase + 15 >= kt * 64) {
            float Sa[8][4];
#pragma unroll
            for (int nt = 0; nt < 8; nt++)
#pragma unroll
                for (int r = 0; r < 4; r++) Sa[nt][r] = 0.f;
#pragma unroll
            for (int nt = 0; nt < 8; nt++) {
                const int rb = nt * 8 + gid;
                const int gb = ctid ^ ((rb ^ (rb >> 2)) & 3);
#pragma unroll
                for (int c = 0; c < 4; c++) {
                    float4 bv = *(const float4*)&Ks[c][rb][gb << 2];
                    const unsigned bh0 = __float_as_uint(bv.x);
                    const unsigned bh1 = __float_as_uint(bv.y);
                    const unsigned bl0 = __float_as_uint(bv.z);
                    const unsigned bl1 = __float_as_uint(bv.w);
                    mma_bf16(Sa[nt], qh[c][0], qh[c][1], qh[c][2], qh[c][3], bh0, bh1);
                    mma_bf16(Sa[nt], ql[c][0], ql[c][1], ql[c][2], ql[c][3], bh0, bh1);
                    mma_bf16(Sa[nt], qh[c][0], qh[c][1], qh[c][2], qh[c][3], bl0, bl1);
                }
            }

            const bool need_mask = (kt >= 2 * qt);
#pragma unroll
            for (int nt = 0; nt < 8; nt++) {
                const int col = kt * 64 + nt * 8 + 2 * ctid;
                Sa[nt][0] *= 0.125f; Sa[nt][1] *= 0.125f;
                Sa[nt][2] *= 0.125f; Sa[nt][3] *= 0.125f;
                if (need_mask) {
                    if (col     > qr0) Sa[nt][0] = -INFINITY;
                    if (col + 1 > qr0) Sa[nt][1] = -INFINITY;
                    if (col     > qr1) Sa[nt][2] = -INFINITY;
                    if (col + 1 > qr1) Sa[nt][3] = -INFINITY;
                }
            }

            float cm0 = -INFINITY, cm1 = -INFINITY;
#pragma unroll
            for (int nt = 0; nt < 8; nt++) {
                cm0 = fmaxf(cm0, fmaxf(Sa[nt][0], Sa[nt][1]));
                cm1 = fmaxf(cm1, fmaxf(Sa[nt][2], Sa[nt][3]));
            }
            cm0 = fmaxf(cm0, __shfl_xor_sync(0xffffffffu, cm0, 1));
            cm0 = fmaxf(cm0, __shfl_xor_sync(0xffffffffu, cm0, 2));
            cm1 = fmaxf(cm1, __shfl_xor_sync(0xffffffffu, cm1, 1));
            cm1 = fmaxf(cm1, __shfl_xor_sync(0xffffffffu, cm1, 2));

            const float mn0 = fmaxf(m0, cm0);
            const float mn1 = fmaxf(m1, cm1);
            const float sc0 = __expf(m0 - mn0);
            const float sc1 = __expf(m1 - mn1);
            m0 = mn0; m1 = mn1;
            l0 *= sc0; l1 *= sc1;
#pragma unroll
            for (int nt = 0; nt < 8; nt++) {
                Oa[nt][0] *= sc0; Oa[nt][1] *= sc0;
                Oa[nt][2] *= sc1; Oa[nt][3] *= sc1;
            }

            float ps0 = 0.f, ps1 = 0.f;
#pragma unroll
            for (int nt = 0; nt < 8; nt++) {
                float p0 = __expf(Sa[nt][0] - m0);
                float p1 = __expf(Sa[nt][1] - m0);
                float p2 = __expf(Sa[nt][2] - m1);
                float p3 = __expf(Sa[nt][3] - m1);
                Sa[nt][0] = p0; Sa[nt][1] = p1; Sa[nt][2] = p2; Sa[nt][3] = p3;
                ps0 += p0 + p1; ps1 += p2 + p3;
            }
            l0 += ps0; l1 += ps1;

#pragma unroll
            for (int c = 0; c < 4; c++) {
                unsigned ph0, pl0, ph1, pl1, ph2, pl2, ph3, pl3;
                split2(Sa[2 * c][0],     Sa[2 * c][1],     ph0, pl0);
                split2(Sa[2 * c][2],     Sa[2 * c][3],     ph1, pl1);
                split2(Sa[2 * c + 1][0], Sa[2 * c + 1][1], ph2, pl2);
                split2(Sa[2 * c + 1][2], Sa[2 * c + 1][3], ph3, pl3);
#pragma unroll
                for (int nt = 0; nt < 8; nt++) {
                    const int rb = nt * 8 + gid;
                    const int gb = ctid ^ ((rb ^ (rb >> 2)) & 3);
                    float4 vv = *(const float4*)&Vs[c][rb][gb << 2];
                    const unsigned vh0 = __float_as_uint(vv.x);
                    const unsigned vh1 = __float_as_uint(vv.y);
                    const unsigned vl0 = __float_as_uint(vv.z);
                    const unsigned vl1 = __float_as_uint(vv.w);
                    mma_bf16(Oa[nt], ph0, ph1, ph2, ph3, vh0, vh1);
                    mma_bf16(Oa[nt], pl0, pl1, pl2, pl3, vh0, vh1);
                    mma_bf16(Oa[nt], ph0, ph1, ph2, ph3, vl0, vl1);
                }
            }
        }
        __syncthreads();
    }

    l0 += __shfl_xor_sync(0xffffffffu, l0, 1);
    l0 += __shfl_xor_sync(0xffffffffu, l0, 2);
    l1 += __shfl_xor_sync(0xffffffffu, l1, 1);
    l1 += __shfl_xor_sync(0xffffffffu, l1, 2);
    const float inv0 = 1.f / l0;
    const float inv1 = 1.f / l1;

    float* y0 = y + (long)(b * T_ + qr0) * C_ + h * HS;
    float* y1 = y + (long)(b * T_ + qr1) * C_ + h * HS;
#pragma unroll
    for (int nt = 0; nt < 8; nt++) {
        const int cc = nt * 8 + 2 * ctid;
        *(float2*)(y0 + cc) = make_float2(Oa[nt][0] * inv0, Oa[nt][1] * inv0);
        *(float2*)(y1 + cc) = make_float2(Oa[nt][2] * inv1, Oa[nt][3] * inv1);
    }
}

// ---------------------------------------------------------------------------
extern "C" void kernel_launch(void* const* d_in, const int* in_sizes, int n_in,
                              void* d_out, int out_size)
{
    const float* x    = (const float*)d_in[0];
    const float* watt = (const float*)d_in[1];
    const float* wprj = (const float*)d_in[2];
    float* out = (float*)d_out;

    float *qkv, *y;
    unsigned *xp, *wattp, *wprjp, *yp;
    cudaGetSymbolAddress((void**)&qkv,   g_qkv);
    cudaGetSymbolAddress((void**)&y,     g_y);
    cudaGetSymbolAddress((void**)&xp,    g_xp);
    cudaGetSymbolAddress((void**)&wattp, g_wattp);
    cudaGetSymbolAddress((void**)&wprjp, g_wprjp);
    cudaGetSymbolAddress((void**)&yp,    g_yp);

    const int MR = B_ * T_;   // 8192

    // pack inputs
    pack_bf16x3<<<(MR * C_ / 16 + 255) / 256, 256>>>(x,    xp,    MR * C_ / 16, C_);
    pack_bf16x3<<<(C3 * C_ / 16 + 255) / 256, 256>>>(watt, wattp, C3 * C_ / 16, C_);
    pack_bf16x3<<<(C_ * C_ / 16 + 255) / 256, 256>>>(wprj, wprjp, C_ * C_ / 16, C_);

    // qkv = x @ w_attn^T
    dim3 g1(C3 / 128, MR / 128);
    gemm_packed<<<g1, 256>>>(xp, wattp, qkv, MR, C3, C_);

    // attention
    dim3 g2(T_ / 128, NH, B_);
    attn_mma<<<g2, 256>>>(qkv, y);

    // pack y, then out = y @ w_proj^T
    pack_bf16x3<<<(MR * C_ / 16 + 255) / 256, 256>>>(y, yp, MR * C_ / 16, C_);
    dim3 g3(C_ / 128, MR / 128);
    gemm_packed<<<g3, 256>>>(yp, wprjp, out, MR, C_, C_);
}

// round 12
// speedup vs baseline: 2.9849x; 1.0409x over previous
#include <cuda_runtime.h>
#include <math.h>

// Problem constants
#define B_  4
#define T_  2048
#define C_  1024
#define NH  16
#define HS  64
#define C3  3072   // 3*C

// Scratch (no allocations allowed)
__device__ float    g_qkv[B_ * T_ * C3];
__device__ float    g_y[B_ * T_ * C_];
__device__ unsigned g_xp[B_ * T_ * C_];     // packed x
__device__ unsigned g_wattp[C3 * C_];       // packed w_attn
__device__ unsigned g_wprjp[C_ * C_];       // packed w_proj
__device__ unsigned g_yp[B_ * T_ * C_];     // packed y
__device__ unsigned g_kp[B_ * NH * T_ * HS]; // packed K  (tile layout)
__device__ unsigned g_vp[B_ * NH * T_ * HS]; // packed V^T (tile layout)

// ---------------------------------------------------------------------------
// bf16x3 helpers (validated R6/R7/R11)
// ---------------------------------------------------------------------------
__device__ __forceinline__ void split2(float x0, float x1, unsigned& hw, unsigned& lw)
{
    const unsigned w0 = __float_as_uint(x0);
    const unsigned w1 = __float_as_uint(x1);
    hw = (w0 >> 16) | (w1 & 0xffff0000u);
    const float r0 = x0 - __uint_as_float(w0 & 0xffff0000u);   // exact
    const float r1 = x1 - __uint_as_float(w1 & 0xffff0000u);   // exact
    asm("cvt.rn.bf16x2.f32 %0, %1, %2;" : "=r"(lw) : "f"(r1), "f"(r0));
}

__device__ __forceinline__ void mma_bf16(
    float* d, unsigned a0, unsigned a1, unsigned a2, unsigned a3,
    unsigned b0, unsigned b1)
{
    asm volatile(
        "mma.sync.aligned.m16n8k16.row.col.f32.bf16.bf16.f32 "
        "{%0,%1,%2,%3}, {%4,%5,%6,%7}, {%8,%9}, {%0,%1,%2,%3};\n"
        : "+f"(d[0]), "+f"(d[1]), "+f"(d[2]), "+f"(d[3])
        : "r"(a0), "r"(a1), "r"(a2), "r"(a3), "r"(b0), "r"(b1));
}

__device__ __forceinline__ void cp16(unsigned smem_addr, const void* gptr)
{
    asm volatile("cp.async.cg.shared.global [%0], [%1], 16;"
                 :: "r"(smem_addr), "l"(gptr));
}

// ---------------------------------------------------------------------------
// Pack fp32 [rows,K] -> 16-word swizzled bf16x3 chunks (validated R11)
// ---------------------------------------------------------------------------
__global__ __launch_bounds__(256) void pack_bf16x3(
    const float* __restrict__ in, unsigned* __restrict__ out, int total, int K)
{
    const int idx = blockIdx.x * 256 + threadIdx.x;
    if (idx >= total) return;
    const int nck = K / 16;
    const int row = idx / nck;
    const int c   = idx % nck;
    const int r   = row & 127;
    const int swz = (r ^ (r >> 2)) & 3;

    const float* p = in + (long)row * K + c * 16;
    unsigned w[16];
#pragma unroll
    for (int j = 0; j < 8; j++) {
        unsigned hw, lw;
        split2(p[2 * j], p[2 * j + 1], hw, lw);
        const int pos = (((j & 3) ^ swz) << 2) + (j >> 2);
        w[pos]     = hw;
        w[pos + 2] = lw;
    }
    uint4* o = (uint4*)(out + (long)row * K + c * 16);
    o[0] = make_uint4(w[0],  w[1],  w[2],  w[3]);
    o[1] = make_uint4(w[4],  w[5],  w[6],  w[7]);
    o[2] = make_uint4(w[8],  w[9],  w[10], w[11]);
    o[3] = make_uint4(w[12], w[13], w[14], w[15]);
}

// ---------------------------------------------------------------------------
// pack_k: K rows of qkv -> tile layout [bh][tile(32)][chunk(4)][key(64)][16w]
// thread = (b,h,key,chunk); pairs over hs. swz from key row within tile.
// ---------------------------------------------------------------------------
__global__ __launch_bounds__(256) void pack_k(
    const float* __restrict__ qkv, unsigned* __restrict__ Kp)
{
    const int idx = blockIdx.x * 256 + threadIdx.x;   // total 524288
    const int c    = idx & 3;
    const int key  = (idx >> 2) & (T_ - 1);
    const int h    = (idx >> 13) & (NH - 1);
    const int b    = idx >> 17;
    const int tile = key >> 6;
    const int r    = key & 63;
    const int swz  = (r ^ (r >> 2)) & 3;

    const float* p = qkv + (long)b * T_ * C3 + (long)key * C3 + C_ + h * HS + c * 16;
    unsigned w[16];
#pragma unroll
    for (int j = 0; j < 8; j++) {
        unsigned hw, lw;
        split2(p[2 * j], p[2 * j + 1], hw, lw);
        const int pos = (((j & 3) ^ swz) << 2) + (j >> 2);
        w[pos]     = hw;
        w[pos + 2] = lw;
    }
    uint4* o = (uint4*)(Kp + ((long)(b * NH + h) * 32 + tile) * 4096 + c * 1024 + r * 16);
    o[0] = make_uint4(w[0],  w[1],  w[2],  w[3]);
    o[1] = make_uint4(w[4],  w[5],  w[6],  w[7]);
    o[2] = make_uint4(w[8],  w[9],  w[10], w[11]);
    o[3] = make_uint4(w[12], w[13], w[14], w[15]);
}

// ---------------------------------------------------------------------------
// pack_v: V^T tile layout [bh][tile][keychunk(4)][hs(64)][16w]; pairs over
// keys (chunk keys vck*16+2jp, +1). swz from hs row. Warp spans consecutive
// hs -> coalesced strided reads.
// ---------------------------------------------------------------------------
__global__ __launch_bounds__(256) void pack_v(
    const float* __restrict__ qkv, unsigned* __restrict__ Vp)
{
    const int idx = blockIdx.x * 256 + threadIdx.x;   // total 524288
    const int hs   = idx & 63;
    const int vck  = (idx >> 6) & 3;
    const int tile = (idx >> 8) & 31;
    const int h    = (idx >> 13) & (NH - 1);
    const int b    = idx >> 17;
    const int swz  = (hs ^ (hs >> 2)) & 3;

    const float* p = qkv + (long)b * T_ * C3
                   + (long)(tile * 64 + vck * 16) * C3 + 2 * C_ + h * HS + hs;
    unsigned w[16];
#pragma unroll
    for (int j = 0; j < 8; j++) {
        const float v0 = p[(2 * j)     * C3];
        const float v1 = p[(2 * j + 1) * C3];
        unsigned hw, lw;
        split2(v0, v1, hw, lw);
        const int pos = (((j & 3) ^ swz) << 2) + (j >> 2);
        w[pos]     = hw;
        w[pos + 2] = lw;
    }
    uint4* o = (uint4*)(Vp + ((long)(b * NH + h) * 32 + tile) * 4096 + vck * 1024 + hs * 16);
    o[0] = make_uint4(w[0],  w[1],  w[2],  w[3]);
    o[1] = make_uint4(w[4],  w[5],  w[6],  w[7]);
    o[2] = make_uint4(w[8],  w[9],  w[10], w[11]);
    o[3] = make_uint4(w[12], w[13], w[14], w[15]);
}

// ---------------------------------------------------------------------------
// Packed GEMM (validated R11): cp.async 3-stage ring, one barrier per stage.
// ---------------------------------------------------------------------------
__global__ __launch_bounds__(256, 2) void gemm_packed(
    const unsigned* __restrict__ Ap, const unsigned* __restrict__ Bp,
    float* __restrict__ Cm, int M, int N, int K)
{
    __shared__ unsigned As[3][2048];
    __shared__ unsigned Bs[3][2048];

    const int tid  = threadIdx.x;
    const int lane = tid & 31;
    const int warp = tid >> 5;
    const int wm   = (warp >> 2) * 64;
    const int wn   = (warp & 3) * 32;
    const int gid  = lane >> 2;
    const int ctid = lane & 3;

    const int m0 = blockIdx.y * 128;
    const int n0 = blockIdx.x * 128;

    const int lrow = tid >> 1;
    const int half = tid & 1;

    const unsigned* Ag = Ap + (long)(m0 + lrow) * K + half * 8;
    const unsigned* Bg = Bp + (long)(n0 + lrow) * K + half * 8;

    const unsigned aBase = (unsigned)__cvta_generic_to_shared(&As[0][0]);
    const unsigned bBase = (unsigned)__cvta_generic_to_shared(&Bs[0][0]);
    const unsigned doff  = (unsigned)(lrow * 16 + half * 8) * 4u;

    float acc[4][4][4];
#pragma unroll
    for (int i = 0; i < 4; i++)
#pragma unroll
        for (int j = 0; j < 4; j++)
#pragma unroll
            for (int r = 0; r < 4; r++) acc[i][j][r] = 0.f;

    const int nstages = K / 16;

#define GP_ISSUE(st) do {                                              \
        const unsigned bufb = ((st) % 3) * 8192u;                      \
        cp16(aBase + bufb + doff,      Ag + (st) * 16);                \
        cp16(aBase + bufb + doff + 16, Ag + (st) * 16 + 4);            \
        cp16(bBase + bufb + doff,      Bg + (st) * 16);                \
        cp16(bBase + bufb + doff + 16, Bg + (st) * 16 + 4);            \
    } while (0)

    GP_ISSUE(0);
    asm volatile("cp.async.commit_group;" ::: "memory");
    GP_ISSUE(1);
    asm volatile("cp.async.commit_group;" ::: "memory");

    int buf = 0;
    for (int s = 0; s < nstages; s++) {
        asm volatile("cp.async.wait_group 1;" ::: "memory");
        __syncthreads();
        if (s + 2 < nstages) GP_ISSUE(s + 2);
        asm volatile("cp.async.commit_group;" ::: "memory");

        const unsigned* Ab = As[buf];
        const unsigned* Bb = Bs[buf];
        buf = (buf == 2) ? 0 : buf + 1;

        uint4 af[4][2];
        uint4 bfr[4];
#pragma unroll
        for (int mt = 0; mt < 4; mt++) {
            const int r0 = wm + mt * 16 + gid;
            const int r1 = r0 + 8;
            const int g0 = ctid ^ ((r0 ^ (r0 >> 2)) & 3);
            const int g1 = ctid ^ ((r1 ^ (r1 >> 2)) & 3);
            af[mt][0] = *(const uint4*)&Ab[r0 * 16 + (g0 << 2)];
            af[mt][1] = *(const uint4*)&Ab[r1 * 16 + (g1 << 2)];
        }
#pragma unroll
        for (int nt = 0; nt < 4; nt++) {
            const int rb = wn + nt * 8 + gid;
            const int gb = ctid ^ ((rb ^ (rb >> 2)) & 3);
            bfr[nt] = *(const uint4*)&Bb[rb * 16 + (gb << 2)];
        }

#pragma unroll
        for (int mt = 0; mt < 4; mt++) {
            const unsigned ah0 = af[mt][0].x, ah1 = af[mt][1].x;
            const unsigned ah2 = af[mt][0].y, ah3 = af[mt][1].y;
            const unsigned al0 = af[mt][0].z, al1 = af[mt][1].z;
            const unsigned al2 = af[mt][0].w, al3 = af[mt][1].w;
#pragma unroll
            for (int nt = 0; nt < 4; nt++) {
                float* d = acc[mt][nt];
                mma_bf16(d, ah0, ah1, ah2, ah3, bfr[nt].x, bfr[nt].y);
                mma_bf16(d, al0, al1, al2, al3, bfr[nt].x, bfr[nt].y);
                mma_bf16(d, ah0, ah1, ah2, ah3, bfr[nt].z, bfr[nt].w);
            }
        }
    }
#undef GP_ISSUE

#pragma unroll
    for (int mt = 0; mt < 4; mt++) {
        const int r0 = m0 + wm + mt * 16 + gid;
#pragma unroll
        for (int nt = 0; nt < 4; nt++) {
            const int c = n0 + wn + nt * 8 + 2 * ctid;
            *(float2*)(Cm + (long)r0 * N + c)       = make_float2(acc[mt][nt][0], acc[mt][nt][1]);
            *(float2*)(Cm + (long)(r0 + 8) * N + c) = make_float2(acc[mt][nt][2], acc[mt][nt][3]);
        }
    }
}

// ---------------------------------------------------------------------------
// Attention v3: K/V pre-packed; inner loop = cp.async 3-stage ring (96KB
// dynamic smem), one barrier per tile, zero in-loop conversion.
// Stage layout: [K 4096w][V 4096w] at stage*8192 words.
// ---------------------------------------------------------------------------
extern __shared__ unsigned AtSm[];

__global__ __launch_bounds__(256) void attn_packed(
    const float* __restrict__ qkv,
    const unsigned* __restrict__ Kp, const unsigned* __restrict__ Vp,
    float* __restrict__ y)
{
    const int qt   = (int)gridDim.x - 1 - (int)blockIdx.x;
    const int h    = blockIdx.y;
    const int b    = blockIdx.z;
    const int tid  = threadIdx.x;
    const int lane = tid & 31;
    const int warp = tid >> 5;
    const int gid  = lane >> 2;
    const int ctid = lane & 3;
    const int qbase = qt * 128 + warp * 16;
    const int qr0 = qbase + gid;
    const int qr1 = qr0 + 8;

    const float* base = qkv + (long)b * T_ * C3;
    const unsigned* Kg = Kp + (long)(b * NH + h) * 32 * 4096;
    const unsigned* Vg = Vp + (long)(b * NH + h) * 32 * 4096;

    const unsigned smBase = (unsigned)__cvta_generic_to_shared(AtSm);
    const unsigned coff   = (unsigned)tid * 64u;   // bytes: 16 words per thread

    // ---- Q fragments (hi/lo), loaded once
    unsigned qh[4][4], ql[4][4];
#pragma unroll
    for (int c = 0; c < 4; c++) {
        const float* q0p = base + (long)qr0 * C3 + h * HS + c * 16;
        const float* q1p = base + (long)qr1 * C3 + h * HS + c * 16;
        float2 x00 = *(const float2*)(q0p + 2 * ctid);
        float2 x10 = *(const float2*)(q1p + 2 * ctid);
        float2 x01 = *(const float2*)(q0p + 8 + 2 * ctid);
        float2 x11 = *(const float2*)(q1p + 8 + 2 * ctid);
        split2(x00.x, x00.y, qh[c][0], ql[c][0]);
        split2(x10.x, x10.y, qh[c][1], ql[c][1]);
        split2(x01.x, x01.y, qh[c][2], ql[c][2]);
        split2(x11.x, x11.y, qh[c][3], ql[c][3]);
    }

    float Oa[8][4];
#pragma unroll
    for (int nt = 0; nt < 8; nt++)
#pragma unroll
        for (int r = 0; r < 4; r++) Oa[nt][r] = 0.f;
    float m0 = -INFINITY, m1 = -INFINITY, l0 = 0.f, l1 = 0.f;

    const int ntiles = 2 * qt + 2;   // always >= 2

#define AT_ISSUE(kt) do {                                              \
        const unsigned sb = ((kt) % 3) * 32768u;                       \
        const unsigned* kg = Kg + (long)(kt) * 4096 + tid * 16;        \
        const unsigned* vg = Vg + (long)(kt) * 4096 + tid * 16;        \
        cp16(smBase + sb + coff,           kg);                        \
        cp16(smBase + sb + coff + 16,      kg + 4);                    \
        cp16(smBase + sb + coff + 32,      kg + 8);                    \
        cp16(smBase + sb + coff + 48,      kg + 12);                   \
        cp16(smBase + sb + 16384 + coff,      vg);                     \
        cp16(smBase + sb + 16384 + coff + 16, vg + 4);                 \
        cp16(smBase + sb + 16384 + coff + 32, vg + 8);                 \
        cp16(smBase + sb + 16384 + coff + 48, vg + 12);                \
    } while (0)

    AT_ISSUE(0);
    asm volatile("cp.async.commit_group;" ::: "memory");
    AT_ISSUE(1);
    asm volatile("cp.async.commit_group;" ::: "memory");

    for (int kt = 0; kt < ntiles; kt++) {
        asm volatile("cp.async.wait_group 1;" ::: "memory");
        __syncthreads();
        if (kt + 2 < ntiles) AT_ISSUE(kt + 2);
        asm volatile("cp.async.commit_group;" ::: "memory");

        const unsigned* Kb = AtSm + (kt % 3) * 8192;
        const unsigned* Vb = Kb + 4096;

        if (qbase + 15 >= kt * 64) {
            // ---- S = Q K^T (bf16x3)
            float Sa[8][4];
#pragma unroll
            for (int nt = 0; nt < 8; nt++)
#pragma unroll
                for (int r = 0; r < 4; r++) Sa[nt][r] = 0.f;
#pragma unroll
            for (int nt = 0; nt < 8; nt++) {
                const int rb = nt * 8 + gid;
                const int gb = ctid ^ ((rb ^ (rb >> 2)) & 3);
#pragma unroll
                for (int c = 0; c < 4; c++) {
                    const uint4 bv = *(const uint4*)&Kb[c * 1024 + rb * 16 + (gb << 2)];
                    mma_bf16(Sa[nt], qh[c][0], qh[c][1], qh[c][2], qh[c][3], bv.x, bv.y);
                    mma_bf16(Sa[nt], ql[c][0], ql[c][1], ql[c][2], ql[c][3], bv.x, bv.y);
                    mma_bf16(Sa[nt], qh[c][0], qh[c][1], qh[c][2], qh[c][3], bv.z, bv.w);
                }
            }

            // ---- scale + causal mask
            const bool need_mask = (kt >= 2 * qt);
#pragma unroll
            for (int nt = 0; nt < 8; nt++) {
                const int col = kt * 64 + nt * 8 + 2 * ctid;
                Sa[nt][0] *= 0.125f; Sa[nt][1] *= 0.125f;
                Sa[nt][2] *= 0.125f; Sa[nt][3] *= 0.125f;
                if (need_mask) {
                    if (col     > qr0) Sa[nt][0] = -INFINITY;
                    if (col + 1 > qr0) Sa[nt][1] = -INFINITY;
                    if (col     > qr1) Sa[nt][2] = -INFINITY;
                    if (col + 1 > qr1) Sa[nt][3] = -INFINITY;
                }
            }

            // ---- online softmax
            float cm0 = -INFINITY, cm1 = -INFINITY;
#pragma unroll
            for (int nt = 0; nt < 8; nt++) {
                cm0 = fmaxf(cm0, fmaxf(Sa[nt][0], Sa[nt][1]));
                cm1 = fmaxf(cm1, fmaxf(Sa[nt][2], Sa[nt][3]));
            }
            cm0 = fmaxf(cm0, __shfl_xor_sync(0xffffffffu, cm0, 1));
            cm0 = fmaxf(cm0, __shfl_xor_sync(0xffffffffu, cm0, 2));
            cm1 = fmaxf(cm1, __shfl_xor_sync(0xffffffffu, cm1, 1));
            cm1 = fmaxf(cm1, __shfl_xor_sync(0xffffffffu, cm1, 2));

            const float mn0 = fmaxf(m0, cm0);
            const float mn1 = fmaxf(m1, cm1);
            const float sc0 = __expf(m0 - mn0);
            const float sc1 = __expf(m1 - mn1);
            m0 = mn0; m1 = mn1;
            l0 *= sc0; l1 *= sc1;
#pragma unroll
            for (int nt = 0; nt < 8; nt++) {
                Oa[nt][0] *= sc0; Oa[nt][1] *= sc0;
                Oa[nt][2] *= sc1; Oa[nt][3] *= sc1;
            }

            float ps0 = 0.f, ps1 = 0.f;
#pragma unroll
            for (int nt = 0; nt < 8; nt++) {
                float p0 = __expf(Sa[nt][0] - m0);
                float p1 = __expf(Sa[nt][1] - m0);
                float p2 = __expf(Sa[nt][2] - m1);
                float p3 = __expf(Sa[nt][3] - m1);
                Sa[nt][0] = p0; Sa[nt][1] = p1; Sa[nt][2] = p2; Sa[nt][3] = p3;
                ps0 += p0 + p1; ps1 += p2 + p3;
            }
            l0 += ps0; l1 += ps1;

            // ---- O += P V (bf16x3)
#pragma unroll
            for (int c = 0; c < 4; c++) {
                unsigned ph0, pl0, ph1, pl1, ph2, pl2, ph3, pl3;
                split2(Sa[2 * c][0],     Sa[2 * c][1],     ph0, pl0);
                split2(Sa[2 * c][2],     Sa[2 * c][3],     ph1, pl1);
                split2(Sa[2 * c + 1][0], Sa[2 * c + 1][1], ph2, pl2);
                split2(Sa[2 * c + 1][2], Sa[2 * c + 1][3], ph3, pl3);
#pragma unroll
                for (int nt = 0; nt < 8; nt++) {
                    const int rb = nt * 8 + gid;
                    const int gb = ctid ^ ((rb ^ (rb >> 2)) & 3);
                    const uint4 vv = *(const uint4*)&Vb[c * 1024 + rb * 16 + (gb << 2)];
                    mma_bf16(Oa[nt], ph0, ph1, ph2, ph3, vv.x, vv.y);
                    mma_bf16(Oa[nt], pl0, pl1, pl2, pl3, vv.x, vv.y);
                    mma_bf16(Oa[nt], ph0, ph1, ph2, ph3, vv.z, vv.w);
                }
            }
        }
    }
#undef AT_ISSUE

    // ---- finalize
    l0 += __shfl_xor_sync(0xffffffffu, l0, 1);
    l0 += __shfl_xor_sync(0xffffffffu, l0, 2);
    l1 += __shfl_xor_sync(0xffffffffu, l1, 1);
    l1 += __shfl_xor_sync(0xffffffffu, l1, 2);
    const float inv0 = 1.f / l0;
    const float inv1 = 1.f / l1;

    float* y0 = y + (long)(b * T_ + qr0) * C_ + h * HS;
    float* y1 = y + (long)(b * T_ + qr1) * C_ + h * HS;
#pragma unroll
    for (int nt = 0; nt < 8; nt++) {
        const int cc = nt * 8 + 2 * ctid;
        *(float2*)(y0 + cc) = make_float2(Oa[nt][0] * inv0, Oa[nt][1] * inv0);
        *(float2*)(y1 + cc) = make_float2(Oa[nt][2] * inv1, Oa[nt][3] * inv1);
    }
}

// ---------------------------------------------------------------------------
extern "C" void kernel_launch(void* const* d_in, const int* in_sizes, int n_in,
                              void* d_out, int out_size)
{
    const float* x    = (const float*)d_in[0];
    const float* watt = (const float*)d_in[1];
    const float* wprj = (const float*)d_in[2];
    float* out = (float*)d_out;

    float *qkv, *y;
    unsigned *xp, *wattp, *wprjp, *yp, *kp, *vp;
    cudaGetSymbolAddress((void**)&qkv,   g_qkv);
    cudaGetSymbolAddress((void**)&y,     g_y);
    cudaGetSymbolAddress((void**)&xp,    g_xp);
    cudaGetSymbolAddress((void**)&wattp, g_wattp);
    cudaGetSymbolAddress((void**)&wprjp, g_wprjp);
    cudaGetSymbolAddress((void**)&yp,    g_yp);
    cudaGetSymbolAddress((void**)&kp,    g_kp);
    cudaGetSymbolAddress((void**)&vp,    g_vp);

    static int smem_set = 0;
    if (!smem_set) {
        cudaFuncSetAttribute(attn_packed,
                             cudaFuncAttributeMaxDynamicSharedMemorySize, 98304);
        smem_set = 1;
    }

    const int MR = B_ * T_;   // 8192

    // pack inputs
    pack_bf16x3<<<(MR * C_ / 16 + 255) / 256, 256>>>(x,    xp,    MR * C_ / 16, C_);
    pack_bf16x3<<<(C3 * C_ / 16 + 255) / 256, 256>>>(watt, wattp, C3 * C_ / 16, C_);
    pack_bf16x3<<<(C_ * C_ / 16 + 255) / 256, 256>>>(wprj, wprjp, C_ * C_ / 16, C_);

    // qkv = x @ w_attn^T
    dim3 g1(C3 / 128, MR / 128);
    gemm_packed<<<g1, 256>>>(xp, wattp, qkv, MR, C3, C_);

    // pack K and V^T tiles
    pack_k<<<2048, 256>>>(qkv, kp);
    pack_v<<<2048, 256>>>(qkv, vp);

    // attention
    dim3 g2(T_ / 128, NH, B_);
    attn_packed<<<g2, 256, 98304>>>(qkv, kp, vp, y);

    // pack y, then out = y @ w_proj^T
    pack_bf16x3<<<(MR * C_ / 16 + 255) / 256, 256>>>(y, yp, MR * C_ / 16, C_);
    dim3 g3(C_ / 128, MR / 128);
    gemm_packed<<<g3, 256>>>(yp, wprjp, out, MR, C_, C_);
}

// round 15
// speedup vs baseline: 3.2646x; 1.0937x over previous
#include <cuda_runtime.h>
#include <cstdint>
#include <math.h>

// Problem constants
#define B_  4
#define T_  2048
#define C_  1024
#define NH  16
#define HS  64
#define C3  3072   // 3*C

// Scratch (no allocations allowed)
__device__ float    g_qkv[B_ * T_ * C3];
__device__ float    g_y[B_ * T_ * C_];
__device__ unsigned g_xp[B_ * T_ * C_];      // packed x
__device__ unsigned g_wattp[C3 * C_];        // packed w_attn
__device__ unsigned g_wprjp[C_ * C_];        // packed w_proj
__device__ unsigned g_yp[B_ * T_ * C_];      // packed y
__device__ unsigned g_kp[B_ * NH * T_ * HS]; // packed K tiles
__device__ unsigned g_vp[B_ * NH * T_ * HS]; // packed V^T tiles

// ---------------------------------------------------------------------------
// bf16x3 helpers (validated R6..R12)
// ---------------------------------------------------------------------------
__device__ __forceinline__ void split2(float x0, float x1, unsigned& hw, unsigned& lw)
{
    const unsigned w0 = __float_as_uint(x0);
    const unsigned w1 = __float_as_uint(x1);
    hw = (w0 >> 16) | (w1 & 0xffff0000u);
    const float r0 = x0 - __uint_as_float(w0 & 0xffff0000u);   // exact
    const float r1 = x1 - __uint_as_float(w1 & 0xffff0000u);   // exact
    asm("cvt.rn.bf16x2.f32 %0, %1, %2;" : "=r"(lw) : "f"(r1), "f"(r0));
}

__device__ __forceinline__ void mma_bf16(
    float* d, unsigned a0, unsigned a1, unsigned a2, unsigned a3,
    unsigned b0, unsigned b1)
{
    asm volatile(
        "mma.sync.aligned.m16n8k16.row.col.f32.bf16.bf16.f32 "
        "{%0,%1,%2,%3}, {%4,%5,%6,%7}, {%8,%9}, {%0,%1,%2,%3};\n"
        : "+f"(d[0]), "+f"(d[1]), "+f"(d[2]), "+f"(d[3])
        : "r"(a0), "r"(a1), "r"(a2), "r"(a3), "r"(b0), "r"(b1));
}

__device__ __forceinline__ void cp16(unsigned smem_addr, const void* gptr)
{
    asm volatile("cp.async.cg.shared.global [%0], [%1], 16;"
                 :: "r"(smem_addr), "l"(gptr));
}

// ---------------------------------------------------------------------------
// Pack fp32 [rows,K] -> 16-word swizzled bf16x3 chunks (validated R11)
// ---------------------------------------------------------------------------
__global__ __launch_bounds__(256) void pack_bf16x3(
    const float* __restrict__ in, unsigned* __restrict__ out, int total, int K)
{
    const int idx = blockIdx.x * 256 + threadIdx.x;
    if (idx >= total) return;
    const int nck = K / 16;
    const int row = idx / nck;
    const int c   = idx % nck;
    const int r   = row & 127;
    const int swz = (r ^ (r >> 2)) & 3;

    const float* p = in + (long)row * K + c * 16;
    unsigned w[16];
#pragma unroll
    for (int j = 0; j < 8; j++) {
        unsigned hw, lw;
        split2(p[2 * j], p[2 * j + 1], hw, lw);
        const int pos = (((j & 3) ^ swz) << 2) + (j >> 2);
        w[pos]     = hw;
        w[pos + 2] = lw;
    }
    uint4* o = (uint4*)(out + (long)row * K + c * 16);
    o[0] = make_uint4(w[0],  w[1],  w[2],  w[3]);
    o[1] = make_uint4(w[4],  w[5],  w[6],  w[7]);
    o[2] = make_uint4(w[8],  w[9],  w[10], w[11]);
    o[3] = make_uint4(w[12], w[13], w[14], w[15]);
}

// ---------------------------------------------------------------------------
// pack_k / pack_v (unchanged from R12, validated)
// ---------------------------------------------------------------------------
__global__ __launch_bounds__(256) void pack_k(
    const float* __restrict__ qkv, unsigned* __restrict__ Kp)
{
    const int idx = blockIdx.x * 256 + threadIdx.x;
    const int c    = idx & 3;
    const int key  = (idx >> 2) & (T_ - 1);
    const int h    = (idx >> 13) & (NH - 1);
    const int b    = idx >> 17;
    const int tile = key >> 6;
    const int r    = key & 63;
    const int swz  = (r ^ (r >> 2)) & 3;

    const float* p = qkv + (long)b * T_ * C3 + (long)key * C3 + C_ + h * HS + c * 16;
    unsigned w[16];
#pragma unroll
    for (int j = 0; j < 8; j++) {
        unsigned hw, lw;
        split2(p[2 * j], p[2 * j + 1], hw, lw);
        const int pos = (((j & 3) ^ swz) << 2) + (j >> 2);
        w[pos]     = hw;
        w[pos + 2] = lw;
    }
    uint4* o = (uint4*)(Kp + ((long)(b * NH + h) * 32 + tile) * 4096 + c * 1024 + r * 16);
    o[0] = make_uint4(w[0],  w[1],  w[2],  w[3]);
    o[1] = make_uint4(w[4],  w[5],  w[6],  w[7]);
    o[2] = make_uint4(w[8],  w[9],  w[10], w[11]);
    o[3] = make_uint4(w[12], w[13], w[14], w[15]);
}

__global__ __launch_bounds__(256) void pack_v(
    const float* __restrict__ qkv, unsigned* __restrict__ Vp)
{
    const int idx = blockIdx.x * 256 + threadIdx.x;
    const int hs   = idx & 63;
    const int vck  = (idx >> 6) & 3;
    const int tile = (idx >> 8) & 31;
    const int h    = (idx >> 13) & (NH - 1);
    const int b    = idx >> 17;
    const int swz  = (hs ^ (hs >> 2)) & 3;

    const float* p = qkv + (long)b * T_ * C3
                   + (long)(tile * 64 + vck * 16) * C3 + 2 * C_ + h * HS + hs;
    unsigned w[16];
#pragma unroll
    for (int j = 0; j < 8; j++) {
        const float v0 = p[(2 * j)     * C3];
        const float v1 = p[(2 * j + 1) * C3];
        unsigned hw, lw;
        split2(v0, v1, hw, lw);
        const int pos = (((j & 3) ^ swz) << 2) + (j >> 2);
        w[pos]     = hw;
        w[pos + 2] = lw;
    }
    uint4* o = (uint4*)(Vp + ((long)(b * NH + h) * 32 + tile) * 4096 + vck * 1024 + hs * 16);
    o[0] = make_uint4(w[0],  w[1],  w[2],  w[3]);
    o[1] = make_uint4(w[4],  w[5],  w[6],  w[7]);
    o[2] = make_uint4(w[8],  w[9],  w[10], w[11]);
    o[3] = make_uint4(w[12], w[13], w[14], w[15]);
}

// ---------------------------------------------------------------------------
// Packed GEMM v3: 4-stage cp.async ring (64KB dynamic smem), wait_group 2,
// unconditional commits. Layout: A stages [0,32KB), B stages [32KB,64KB).
// ---------------------------------------------------------------------------
extern __shared__ unsigned GSm[];

__global__ __launch_bounds__(256, 2) void gemm_packed(
    const unsigned* __restrict__ Ap, const unsigned* __restrict__ Bp,
    float* __restrict__ Cm, int M, int N, int K)
{
    const int tid  = threadIdx.x;
    const int lane = tid & 31;
    const int warp = tid >> 5;
    const int wm   = (warp >> 2) * 64;
    const int wn   = (warp & 3) * 32;
    const int gid  = lane >> 2;
    const int ctid = lane & 3;

    const int m0 = blockIdx.y * 128;
    const int n0 = blockIdx.x * 128;

    const int lrow = tid >> 1;
    const int half = tid & 1;

    const unsigned* Ag = Ap + (long)(m0 + lrow) * K + half * 8;
    const unsigned* Bg = Bp + (long)(n0 + lrow) * K + half * 8;

    const unsigned aBase = (unsigned)__cvta_generic_to_shared(GSm);
    const unsigned bBase = aBase + 32768u;
    const unsigned doff  = (unsigned)(lrow * 16 + half * 8) * 4u;

    float acc[4][4][4];
#pragma unroll
    for (int i = 0; i < 4; i++)
#pragma unroll
        for (int j = 0; j < 4; j++)
#pragma unroll
            for (int r = 0; r < 4; r++) acc[i][j][r] = 0.f;

    const int nstages = K / 16;

#define GP_ISSUE(st) do {                                              \
        const unsigned bufb = ((st) & 3) * 8192u;                      \
        cp16(aBase + bufb + doff,      Ag + (st) * 16);                \
        cp16(aBase + bufb + doff + 16, Ag + (st) * 16 + 4);            \
        cp16(bBase + bufb + doff,      Bg + (st) * 16);                \
        cp16(bBase + bufb + doff + 16, Bg + (st) * 16 + 4);            \
    } while (0)

    GP_ISSUE(0);
    asm volatile("cp.async.commit_group;" ::: "memory");
    GP_ISSUE(1);
    asm volatile("cp.async.commit_group;" ::: "memory");
    GP_ISSUE(2);
    asm volatile("cp.async.commit_group;" ::: "memory");

    for (int s = 0; s < nstages; s++) {
        asm volatile("cp.async.wait_group 2;" ::: "memory");
        __syncthreads();
        if (s + 3 < nstages) GP_ISSUE(s + 3);
        asm volatile("cp.async.commit_group;" ::: "memory");

        const unsigned* Ab = GSm + (s & 3) * 2048;
        const unsigned* Bb = GSm + 8192 + (s & 3) * 2048;

        uint4 af[4][2];
        uint4 bfr[4];
#pragma unroll
        for (int mt = 0; mt < 4; mt++) {
            const int r0 = wm + mt * 16 + gid;
            const int r1 = r0 + 8;
            const int g0 = ctid ^ ((r0 ^ (r0 >> 2)) & 3);
            const int g1 = ctid ^ ((r1 ^ (r1 >> 2)) & 3);
            af[mt][0] = *(const uint4*)&Ab[r0 * 16 + (g0 << 2)];
            af[mt][1] = *(const uint4*)&Ab[r1 * 16 + (g1 << 2)];
        }
#pragma unroll
        for (int nt = 0; nt < 4; nt++) {
            const int rb = wn + nt * 8 + gid;
            const int gb = ctid ^ ((rb ^ (rb >> 2)) & 3);
            bfr[nt] = *(const uint4*)&Bb[rb * 16 + (gb << 2)];
        }

#pragma unroll
        for (int mt = 0; mt < 4; mt++) {
            const unsigned ah0 = af[mt][0].x, ah1 = af[mt][1].x;
            const unsigned ah2 = af[mt][0].y, ah3 = af[mt][1].y;
            const unsigned al0 = af[mt][0].z, al1 = af[mt][1].z;
            const unsigned al2 = af[mt][0].w, al3 = af[mt][1].w;
#pragma unroll
            for (int nt = 0; nt < 4; nt++) {
                float* d = acc[mt][nt];
                mma_bf16(d, ah0, ah1, ah2, ah3, bfr[nt].x, bfr[nt].y);   // Ah*Bh
                mma_bf16(d, al0, al1, al2, al3, bfr[nt].x, bfr[nt].y);   // Al*Bh
                mma_bf16(d, ah0, ah1, ah2, ah3, bfr[nt].z, bfr[nt].w);   // Ah*Bl
            }
        }
    }
#undef GP_ISSUE

#pragma unroll
    for (int mt = 0; mt < 4; mt++) {
        const int r0 = m0 + wm + mt * 16 + gid;
#pragma unroll
        for (int nt = 0; nt < 4; nt++) {
            const int c = n0 + wn + nt * 8 + 2 * ctid;
            *(float2*)(Cm + (long)r0 * N + c)       = make_float2(acc[mt][nt][0], acc[mt][nt][1]);
            *(float2*)(Cm + (long)(r0 + 8) * N + c) = make_float2(acc[mt][nt][2], acc[mt][nt][3]);
        }
    }
}

// ---------------------------------------------------------------------------
// Attention v4: 128-key tiles (2 packed 64-key tiles, contiguous), 2-stage
// cp.async ring (128KB dynamic smem), wait_group 0. Stage: [K 8192w][V 8192w].
// ---------------------------------------------------------------------------
extern __shared__ unsigned AtSm[];

__global__ __launch_bounds__(256) void attn_packed(
    const float* __restrict__ qkv,
    const unsigned* __restrict__ Kp, const unsigned* __restrict__ Vp,
    float* __restrict__ y)
{
    const int qt   = (int)gridDim.x - 1 - (int)blockIdx.x;
    const int h    = blockIdx.y;
    const int b    = blockIdx.z;
    const int tid  = threadIdx.x;
    const int lane = tid & 31;
    const int warp = tid >> 5;
    const int gid  = lane >> 2;
    const int ctid = lane & 3;
    const int qbase = qt * 128 + warp * 16;
    const int qr0 = qbase + gid;
    const int qr1 = qr0 + 8;

    const float* base = qkv + (long)b * T_ * C3;
    const unsigned* Kg = Kp + (long)(b * NH + h) * 32 * 4096;
    const unsigned* Vg = Vp + (long)(b * NH + h) * 32 * 4096;

    const unsigned smBase = (unsigned)__cvta_generic_to_shared(AtSm);

    // ---- Q fragments (hi/lo), loaded once
    unsigned qh[4][4], ql[4][4];
#pragma unroll
    for (int c = 0; c < 4; c++) {
        const float* q0p = base + (long)qr0 * C3 + h * HS + c * 16;
        const float* q1p = base + (long)qr1 * C3 + h * HS + c * 16;
        float2 x00 = *(const float2*)(q0p + 2 * ctid);
        float2 x10 = *(const float2*)(q1p + 2 * ctid);
        float2 x01 = *(const float2*)(q0p + 8 + 2 * ctid);
        float2 x11 = *(const float2*)(q1p + 8 + 2 * ctid);
        split2(x00.x, x00.y, qh[c][0], ql[c][0]);
        split2(x10.x, x10.y, qh[c][1], ql[c][1]);
        split2(x01.x, x01.y, qh[c][2], ql[c][2]);
        split2(x11.x, x11.y, qh[c][3], ql[c][3]);
    }

    float Oa[8][4];
#pragma unroll
    for (int nt = 0; nt < 8; nt++)
#pragma unroll
        for (int r = 0; r < 4; r++) Oa[nt][r] = 0.f;
    float m0 = -INFINITY, m1 = -INFINITY, l0 = 0.f, l1 = 0.f;

    const int ntiles = qt + 1;   // 128-key tiles

#define AT_ISSUE(kt) do {                                              \
        const unsigned sb = smBase + ((kt) & 1) * 65536u;              \
        const unsigned* kg = Kg + (long)(kt) * 8192;                   \
        const unsigned* vg = Vg + (long)(kt) * 8192;                   \
        _Pragma("unroll")                                              \
        for (int i = 0; i < 8; i++) {                                  \
            const int e = i * 256 + tid;                               \
            cp16(sb + e * 16u,           kg + e * 4);                  \
            cp16(sb + 32768u + e * 16u,  vg + e * 4);                  \
        }                                                              \
        asm volatile("cp.async.commit_group;" ::: "memory");           \
    } while (0)

    AT_ISSUE(0);

    for (int kt = 0; kt < ntiles; kt++) {
        asm volatile("cp.async.wait_group 0;" ::: "memory");
        __syncthreads();
        if (kt + 1 < ntiles) AT_ISSUE(kt + 1);

        const unsigned* Kb = AtSm + (kt & 1) * 16384;
        const unsigned* Vb = Kb + 8192;

        // ---- S = Q K^T over 128 keys (bf16x3)
        float Sa[16][4];
#pragma unroll
        for (int nt = 0; nt < 16; nt++)
#pragma unroll
            for (int r = 0; r < 4; r++) Sa[nt][r] = 0.f;
#pragma unroll
        for (int nt = 0; nt < 16; nt++) {
            const int rb  = nt * 8 + gid;          // key 0..127
            const int r64 = rb & 63;
            const int gb  = ctid ^ ((r64 ^ (r64 >> 2)) & 3);
            const unsigned* Kt = Kb + (rb >> 6) * 4096;
#pragma unroll
            for (int c = 0; c < 4; c++) {
                const uint4 bv = *(const uint4*)&Kt[c * 1024 + r64 * 16 + (gb << 2)];
                mma_bf16(Sa[nt], qh[c][0], qh[c][1], qh[c][2], qh[c][3], bv.x, bv.y);
                mma_bf16(Sa[nt], ql[c][0], ql[c][1], ql[c][2], ql[c][3], bv.x, bv.y);
                mma_bf16(Sa[nt], qh[c][0], qh[c][1], qh[c][2], qh[c][3], bv.z, bv.w);
            }
        }

        // ---- scale + causal mask (only last tile)
        const bool need_mask = (kt == qt);
#pragma unroll
        for (int nt = 0; nt < 16; nt++) {
            const int col = kt * 128 + nt * 8 + 2 * ctid;
            Sa[nt][0] *= 0.125f; Sa[nt][1] *= 0.125f;
            Sa[nt][2] *= 0.125f; Sa[nt][3] *= 0.125f;
            if (need_mask) {
                if (col     > qr0) Sa[nt][0] = -INFINITY;
                if (col + 1 > qr0) Sa[nt][1] = -INFINITY;
                if (col     > qr1) Sa[nt][2] = -INFINITY;
                if (col + 1 > qr1) Sa[nt][3] = -INFINITY;
            }
        }

        // ---- online softmax
        float cm0 = -INFINITY, cm1 = -INFINITY;
#pragma unroll
        for (int nt = 0; nt < 16; nt++) {
            cm0 = fmaxf(cm0, fmaxf(Sa[nt][0], Sa[nt][1]));
            cm1 = fmaxf(cm1, fmaxf(Sa[nt][2], Sa[nt][3]));
        }
        cm0 = fmaxf(cm0, __shfl_xor_sync(0xffffffffu, cm0, 1));
        cm0 = fmaxf(cm0, __shfl_xor_sync(0xffffffffu, cm0, 2));
        cm1 = fmaxf(cm1, __shfl_xor_sync(0xffffffffu, cm1, 1));
        cm1 = fmaxf(cm1, __shfl_xor_sync(0xffffffffu, cm1, 2));

        const float mn0 = fmaxf(m0, cm0);
        const float mn1 = fmaxf(m1, cm1);
        const float sc0 = __expf(m0 - mn0);
        const float sc1 = __expf(m1 - mn1);
        m0 = mn0; m1 = mn1;
        l0 *= sc0; l1 *= sc1;
#pragma unroll
        for (int nt = 0; nt < 8; nt++) {
            Oa[nt][0] *= sc0; Oa[nt][1] *= sc0;
            Oa[nt][2] *= sc1; Oa[nt][3] *= sc1;
        }

        float ps0 = 0.f, ps1 = 0.f;
#pragma unroll
        for (int nt = 0; nt < 16; nt++) {
            float p0 = __expf(Sa[nt][0] - m0);
            float p1 = __expf(Sa[nt][1] - m0);
            float p2 = __expf(Sa[nt][2] - m1);
            float p3 = __expf(Sa[nt][3] - m1);
            Sa[nt][0] = p0; Sa[nt][1] = p1; Sa[nt][2] = p2; Sa[nt][3] = p3;
            ps0 += p0 + p1; ps1 += p2 + p3;
        }
        l0 += ps0; l1 += ps1;

        // ---- O += P V over 8 key chunks of 16 (bf16x3)
#pragma unroll
        for (int kc = 0; kc < 8; kc++) {
            unsigned ph0, pl0, ph1, pl1, ph2, pl2, ph3, pl3;
            split2(Sa[2 * kc][0],     Sa[2 * kc][1],     ph0, pl0);
            split2(Sa[2 * kc][2],     Sa[2 * kc][3],     ph1, pl1);
            split2(Sa[2 * kc + 1][0], Sa[2 * kc + 1][1], ph2, pl2);
            split2(Sa[2 * kc + 1][2], Sa[2 * kc + 1][3], ph3, pl3);
            const unsigned* Vt = Vb + (kc >> 2) * 4096 + (kc & 3) * 1024;
#pragma unroll
            for (int nt = 0; nt < 8; nt++) {
                const int rb = nt * 8 + gid;   // hs 0..63
                const int gb = ctid ^ ((rb ^ (rb >> 2)) & 3);
                const uint4 vv = *(const uint4*)&Vt[rb * 16 + (gb << 2)];
                mma_bf16(Oa[nt], ph0, ph1, ph2, ph3, vv.x, vv.y);
                mma_bf16(Oa[nt], pl0, pl1, pl2, pl3, vv.x, vv.y);
                mma_bf16(Oa[nt], ph0, ph1, ph2, ph3, vv.z, vv.w);
            }
        }
    }
#undef AT_ISSUE

    // ---- finalize
    l0 += __shfl_xor_sync(0xffffffffu, l0, 1);
    l0 += __shfl_xor_sync(0xffffffffu, l0, 2);
    l1 += __shfl_xor_sync(0xffffffffu, l1, 1);
    l1 += __shfl_xor_sync(0xffffffffu, l1, 2);
    const float inv0 = 1.f / l0;
    const float inv1 = 1.f / l1;

    float* y0 = y + (long)(b * T_ + qr0) * C_ + h * HS;
    float* y1 = y + (long)(b * T_ + qr1) * C_ + h * HS;
#pragma unroll
    for (int nt = 0; nt < 8; nt++) {
        const int cc = nt * 8 + 2 * ctid;
        *(float2*)(y0 + cc) = make_float2(Oa[nt][0] * inv0, Oa[nt][1] * inv0);
        *(float2*)(y1 + cc) = make_float2(Oa[nt][2] * inv1, Oa[nt][3] * inv1);
    }
}

// ---------------------------------------------------------------------------
extern "C" void kernel_launch(void* const* d_in, const int* in_sizes, int n_in,
                              void* d_out, int out_size)
{
    const float* x    = (const float*)d_in[0];
    const float* watt = (const float*)d_in[1];
    const float* wprj = (const float*)d_in[2];
    float* out = (float*)d_out;

    float *qkv, *y;
    unsigned *xp, *wattp, *wprjp, *yp, *kp, *vp;
    cudaGetSymbolAddress((void**)&qkv,   g_qkv);
    cudaGetSymbolAddress((void**)&y,     g_y);
    cudaGetSymbolAddress((void**)&xp,    g_xp);
    cudaGetSymbolAddress((void**)&wattp, g_wattp);
    cudaGetSymbolAddress((void**)&wprjp, g_wprjp);
    cudaGetSymbolAddress((void**)&yp,    g_yp);
    cudaGetSymbolAddress((void**)&kp,    g_kp);
    cudaGetSymbolAddress((void**)&vp,    g_vp);

    static int attr_set = 0;
    if (!attr_set) {
        cudaFuncSetAttribute(gemm_packed,
                             cudaFuncAttributeMaxDynamicSharedMemorySize, 65536);
        cudaFuncSetAttribute(attn_packed,
                             cudaFuncAttributeMaxDynamicSharedMemorySize, 131072);
        attr_set = 1;
    }

    const int MR = B_ * T_;   // 8192

    // pack inputs
    pack_bf16x3<<<(MR * C_ / 16 + 255) / 256, 256>>>(x,    xp,    MR * C_ / 16, C_);
    pack_bf16x3<<<(C3 * C_ / 16 + 255) / 256, 256>>>(watt, wattp, C3 * C_ / 16, C_);
    pack_bf16x3<<<(C_ * C_ / 16 + 255) / 256, 256>>>(wprj, wprjp, C_ * C_ / 16, C_);

    // qkv = x @ w_attn^T
    dim3 g1(C3 / 128, MR / 128);
    gemm_packed<<<g1, 256, 65536>>>(xp, wattp, qkv, MR, C3, C_);

    // pack K and V^T tiles, attention
    pack_k<<<2048, 256>>>(qkv, kp);
    pack_v<<<2048, 256>>>(qkv, vp);
    dim3 g2(T_ / 128, NH, B_);
    attn_packed<<<g2, 256, 131072>>>(qkv, kp, vp, y);

    // pack y, then out = y @ w_proj^T
    pack_bf16x3<<<(MR * C_ / 16 + 255) / 256, 256>>>(y, yp, MR * C_ / 16, C_);
    dim3 g3(C_ / 128, MR / 128);
    gemm_packed<<<g3, 256, 65536>>>(yp, wprjp, out, MR, C_, C_);
}